// round 1
// baseline (speedup 1.0000x reference)
#include <cuda_runtime.h>
#include <math.h>

// Problem constants
#define BB 4
#define LL 2048
#define HIDDEN 2048
#define NH 16
#define HD 128
#define MROWS (BB * LL)          // 8192
#define QKVN (3 * NH * HD)       // 6144
#define NEGBIG -1e30f

// Scratch (static device globals: allocation-free)
__device__ float g_qkv[(size_t)MROWS * QKVN];         // 8192 x 6144
__device__ float g_q[(size_t)BB * NH * LL * HD];      // [b,h,l,d]
__device__ float g_k[(size_t)BB * NH * LL * HD];
__device__ float g_v[(size_t)BB * NH * LL * HD];
__device__ float g_attn[(size_t)MROWS * (NH * HD)];   // 8192 x 2048

// ---------------------------------------------------------------------------
// SGEMM: C[M,N] = A[M,K] @ B[K,N], all row-major fp32.
// 128x128 block tile, K-step 8, 256 threads, 8x8 per-thread register tile.
// M,N,K all divisible by tile dims for this problem (no guards).
// ---------------------------------------------------------------------------
__global__ __launch_bounds__(256) void sgemm128(
    const float* __restrict__ A, const float* __restrict__ Bm,
    float* __restrict__ C, int Kdim, int Ndim)
{
    __shared__ float As[8][128];   // A transposed: As[k][m]
    __shared__ float Bs[8][128];   // Bs[k][n]

    const int tid = threadIdx.x;
    const int brow = blockIdx.y;   // M tile
    const int bcol = blockIdx.x;   // N tile

    const float* Ab = A + (size_t)brow * 128 * Kdim;
    const float* Bb = Bm + (size_t)bcol * 128;

    // A-load mapping: each thread loads one float4 along K
    const int arow = tid >> 1;            // 0..127
    const int acol = (tid & 1) * 4;       // 0 or 4
    // B-load mapping
    const int brw = tid >> 5;             // 0..7
    const int bcl = (tid & 31) * 4;       // 0..124

    const int ty = tid >> 4;              // 0..15
    const int tx = tid & 15;              // 0..15

    float acc[8][8];
#pragma unroll
    for (int i = 0; i < 8; i++)
#pragma unroll
        for (int j = 0; j < 8; j++) acc[i][j] = 0.f;

    for (int k0 = 0; k0 < Kdim; k0 += 8) {
        float4 av = *(const float4*)(Ab + (size_t)arow * Kdim + k0 + acol);
        float4 bv = *(const float4*)(Bb + (size_t)(k0 + brw) * Ndim + bcl);

        __syncthreads();   // previous compute done before overwrite
        As[acol + 0][arow] = av.x;
        As[acol + 1][arow] = av.y;
        As[acol + 2][arow] = av.z;
        As[acol + 3][arow] = av.w;
        *(float4*)&Bs[brw][bcl] = bv;
        __syncthreads();

#pragma unroll
        for (int kk = 0; kk < 8; kk++) {
            float a[8], b[8];
            *(float4*)(a)     = *(float4*)&As[kk][ty * 8];
            *(float4*)(a + 4) = *(float4*)&As[kk][ty * 8 + 4];
            *(float4*)(b)     = *(float4*)&Bs[kk][tx * 8];
            *(float4*)(b + 4) = *(float4*)&Bs[kk][tx * 8 + 4];
#pragma unroll
            for (int i = 0; i < 8; i++)
#pragma unroll
                for (int j = 0; j < 8; j++)
                    acc[i][j] += a[i] * b[j];
        }
    }

    float* Cb = C + (size_t)(brow * 128 + ty * 8) * Ndim + bcol * 128 + tx * 8;
#pragma unroll
    for (int i = 0; i < 8; i++) {
        *(float4*)(Cb + (size_t)i * Ndim)     = *(float4*)&acc[i][0];
        *(float4*)(Cb + (size_t)i * Ndim + 4) = *(float4*)&acc[i][4];
    }
}

// ---------------------------------------------------------------------------
// RoPE + scatter: qkv[8192,6144] -> g_q/g_k (roped, q scaled by 1/sqrt(D)) and
// g_v, all in [b,h,l,d] layout.
// ---------------------------------------------------------------------------
__global__ __launch_bounds__(256) void rope_scatter()
{
    const int idx = blockIdx.x * blockDim.x + threadIdx.x;  // over B*H*L*D
    const int d = idx & (HD - 1);
    const int l = (idx >> 7) & (LL - 1);
    const int h = (idx >> 18) & (NH - 1);
    const int b = idx >> 22;

    const float* row = g_qkv + (size_t)(b * LL + l) * QKVN;
    const float qv = row[h * HD + d];
    const float kv = row[NH * HD + h * HD + d];
    const float vv = row[2 * NH * HD + h * HD + d];

    const int dm = d & 63;
    // inv_freq = 10000^(-2*dm/128); angle = l * inv_freq
    const float inv = expf(-((float)(2 * dm) / 128.f) * 9.210340371976184f);
    const float ang = (float)l * inv;
    float s, c;
    sincosf(ang, &s, &c);

    const int p = (d < 64) ? d + 64 : d - 64;
    const float sgn = (d < 64) ? -1.f : 1.f;
    const float qp = row[h * HD + p];
    const float kp = row[NH * HD + h * HD + p];

    const float scale = 0.08838834764831845f;  // 1/sqrt(128)
    const size_t o = ((size_t)(b * NH + h) * LL + l) * HD + d;
    g_q[o] = (qv * c + sgn * qp * s) * scale;
    g_k[o] = kv * c + sgn * kp * s;
    g_v[o] = vv;
}

// ---------------------------------------------------------------------------
// Flash attention, fp32. BQ=BKV=64, D=128. 256 threads.
// Grid: (L/64, B*H). Causal: only k-tiles kt <= qt processed.
// Output written directly in [b, l, h*D + d] layout for the Wo GEMM.
// ---------------------------------------------------------------------------
#define FLASH_SMEM ((128 * 64 + 128 * 64 + 64 * 128 + 64 * 65) * 4)

__global__ __launch_bounds__(256) void flash_attn_kernel(
    const float* __restrict__ Q, const float* __restrict__ K,
    const float* __restrict__ V, float* __restrict__ Out)
{
    extern __shared__ float sm[];
    float* QT = sm;                 // [128][64]  (d-major)
    float* KT = QT + 128 * 64;      // [128][64]
    float* Vs = KT + 128 * 64;      // [64][128]
    float* Ps = Vs + 64 * 128;      // [64][65]  (padded)

    const int tid = threadIdx.x;
    const int qt = blockIdx.x;
    const int bh = blockIdx.y;

    const float* Qg = Q + ((size_t)bh * LL + qt * 64) * HD;
    const float* Kg = K + (size_t)bh * LL * HD;
    const float* Vg = V + (size_t)bh * LL * HD;

    // Load Q tile transposed
    for (int idx = tid; idx < 64 * 128 / 4; idx += 256) {
        const int row = idx >> 5;
        const int d0 = (idx & 31) * 4;
        float4 v = *(const float4*)(Qg + (size_t)row * HD + d0);
        QT[(d0 + 0) * 64 + row] = v.x;
        QT[(d0 + 1) * 64 + row] = v.y;
        QT[(d0 + 2) * 64 + row] = v.z;
        QT[(d0 + 3) * 64 + row] = v.w;
    }

    const int ty = tid >> 4;  // row group: rows ty*4 .. ty*4+3
    const int tx = tid & 15;  // S: cols tx*4..+3 ; AV: d cols tx*8..+7

    float acc[4][8];
    float m[4], l[4];
#pragma unroll
    for (int r = 0; r < 4; r++) {
        m[r] = NEGBIG; l[r] = 0.f;
#pragma unroll
        for (int c = 0; c < 8; c++) acc[r][c] = 0.f;
    }

    for (int kt = 0; kt <= qt; kt++) {
        const float* Kt = Kg + (size_t)kt * 64 * HD;
        const float* Vt = Vg + (size_t)kt * 64 * HD;

        __syncthreads();  // previous iteration's reads done
        for (int idx = tid; idx < 64 * 128 / 4; idx += 256) {
            const int row = idx >> 5;
            const int d0 = (idx & 31) * 4;
            float4 v = *(const float4*)(Kt + (size_t)row * HD + d0);
            KT[(d0 + 0) * 64 + row] = v.x;
            KT[(d0 + 1) * 64 + row] = v.y;
            KT[(d0 + 2) * 64 + row] = v.z;
            KT[(d0 + 3) * 64 + row] = v.w;
            float4 w = *(const float4*)(Vt + (size_t)row * HD + d0);
            *(float4*)(Vs + (size_t)row * HD + d0) = w;
        }
        __syncthreads();

        // S tile: s[r][c] = sum_d Q[ty*4+r][d] * K[tx*4+c][d]
        float s[4][4];
#pragma unroll
        for (int r = 0; r < 4; r++)
#pragma unroll
            for (int c = 0; c < 4; c++) s[r][c] = 0.f;

        for (int d = 0; d < 128; d++) {
            float qa[4], kb[4];
            *(float4*)qa = *(float4*)&QT[d * 64 + ty * 4];
            *(float4*)kb = *(float4*)&KT[d * 64 + tx * 4];
#pragma unroll
            for (int r = 0; r < 4; r++)
#pragma unroll
                for (int c = 0; c < 4; c++)
                    s[r][c] += qa[r] * kb[c];
        }

        // Causal mask on the diagonal tile
        if (kt == qt) {
#pragma unroll
            for (int r = 0; r < 4; r++)
#pragma unroll
                for (int c = 0; c < 4; c++)
                    if (tx * 4 + c > ty * 4 + r) s[r][c] = NEGBIG;
        }

        // Online softmax row stats (rows shared by the 16 tx threads of a ty)
        float alpha[4];
#pragma unroll
        for (int r = 0; r < 4; r++) {
            float mx = s[r][0];
            mx = fmaxf(mx, s[r][1]); mx = fmaxf(mx, s[r][2]); mx = fmaxf(mx, s[r][3]);
#pragma unroll
            for (int off = 1; off < 16; off <<= 1)
                mx = fmaxf(mx, __shfl_xor_sync(0xFFFFFFFFu, mx, off));
            const float mn = fmaxf(m[r], mx);
            alpha[r] = __expf(m[r] - mn);
            m[r] = mn;
            float rs = 0.f;
#pragma unroll
            for (int c = 0; c < 4; c++) {
                s[r][c] = __expf(s[r][c] - mn);
                rs += s[r][c];
            }
#pragma unroll
            for (int off = 1; off < 16; off <<= 1)
                rs += __shfl_xor_sync(0xFFFFFFFFu, rs, off);
            l[r] = l[r] * alpha[r] + rs;
        }

        // Stage P into smem
#pragma unroll
        for (int r = 0; r < 4; r++)
#pragma unroll
            for (int c = 0; c < 4; c++)
                Ps[(ty * 4 + r) * 65 + tx * 4 + c] = s[r][c];
        __syncthreads();

        // Rescale accumulator, then O += P @ V
#pragma unroll
        for (int r = 0; r < 4; r++)
#pragma unroll
            for (int c = 0; c < 8; c++)
                acc[r][c] *= alpha[r];

        for (int j = 0; j < 64; j++) {
            float p[4];
#pragma unroll
            for (int r = 0; r < 4; r++)
                p[r] = Ps[(ty * 4 + r) * 65 + j];
            float vv[8];
            *(float4*)(vv)     = *(float4*)&Vs[j * 128 + tx * 8];
            *(float4*)(vv + 4) = *(float4*)&Vs[j * 128 + tx * 8 + 4];
#pragma unroll
            for (int r = 0; r < 4; r++)
#pragma unroll
                for (int c = 0; c < 8; c++)
                    acc[r][c] += p[r] * vv[c];
        }
    }

    // Epilogue: divide by softmax denominator, write [b, l, h*D+d]
    const int b = bh >> 4;
    const int h = bh & 15;
#pragma unroll
    for (int r = 0; r < 4; r++) {
        const float inv = 1.f / l[r];
        const int lrow = qt * 64 + ty * 4 + r;
        float* Og = Out + ((size_t)(b * LL + lrow)) * (NH * HD) + h * HD + tx * 8;
        float4 o0, o1;
        o0.x = acc[r][0] * inv; o0.y = acc[r][1] * inv;
        o0.z = acc[r][2] * inv; o0.w = acc[r][3] * inv;
        o1.x = acc[r][4] * inv; o1.y = acc[r][5] * inv;
        o1.z = acc[r][6] * inv; o1.w = acc[r][7] * inv;
        *(float4*)(Og)     = o0;
        *(float4*)(Og + 4) = o1;
    }
}

// ---------------------------------------------------------------------------
extern "C" void kernel_launch(void* const* d_in, const int* in_sizes, int n_in,
                              void* d_out, int out_size)
{
    const float* x    = (const float*)d_in[0];
    const float* Wqkv = (const float*)d_in[1];
    const float* Wo   = (const float*)d_in[2];
    float* out = (float*)d_out;

    float *qkv, *q, *k, *v, *attn;
    cudaGetSymbolAddress((void**)&qkv,  g_qkv);
    cudaGetSymbolAddress((void**)&q,    g_q);
    cudaGetSymbolAddress((void**)&k,    g_k);
    cudaGetSymbolAddress((void**)&v,    g_v);
    cudaGetSymbolAddress((void**)&attn, g_attn);

    cudaFuncSetAttribute(flash_attn_kernel,
                         cudaFuncAttributeMaxDynamicSharedMemorySize, FLASH_SMEM);

    // 1) QKV projection: [8192,2048] @ [2048,6144]
    sgemm128<<<dim3(QKVN / 128, MROWS / 128), 256>>>(x, Wqkv, qkv, HIDDEN, QKVN);

    // 2) RoPE + scatter to [b,h,l,d]
    rope_scatter<<<(BB * NH * LL * HD) / 256, 256>>>();

    // 3) Causal flash attention
    flash_attn_kernel<<<dim3(LL / 64, BB * NH), 256, FLASH_SMEM>>>(q, k, v, attn);

    // 4) Output projection: [8192,2048] @ [2048,2048]
    sgemm128<<<dim3(HIDDEN / 128, MROWS / 128), 256>>>(attn, Wo, out, HIDDEN, HIDDEN);
}

// round 4
// speedup vs baseline: 1.5786x; 1.5786x over previous
#include <cuda_runtime.h>
#include <cuda_bf16.h>
#include <stdint.h>
#include <math.h>

// Problem constants
#define BB 4
#define LL 2048
#define HIDDEN 2048
#define NH 16
#define HD 128
#define MROWS (BB * LL)          // 8192
#define QKVN (3 * NH * HD)       // 6144
#define NEGBIG -1e30f

// fp32 scratch
__device__ float g_qkv[(size_t)MROWS * QKVN];
__device__ float g_q[(size_t)BB * NH * LL * HD];
__device__ float g_k[(size_t)BB * NH * LL * HD];
__device__ float g_v[(size_t)BB * NH * LL * HD];
__device__ float g_attn[(size_t)MROWS * (NH * HD)];

// bf16 split operands
__device__ __nv_bfloat16 g_xh[(size_t)MROWS * HIDDEN];
__device__ __nv_bfloat16 g_xl[(size_t)MROWS * HIDDEN];
__device__ __nv_bfloat16 g_wqh[(size_t)QKVN * HIDDEN];   // Wqkv^T [6144,2048]
__device__ __nv_bfloat16 g_wql[(size_t)QKVN * HIDDEN];
__device__ __nv_bfloat16 g_woh[(size_t)HIDDEN * HIDDEN]; // Wo^T [2048,2048]
__device__ __nv_bfloat16 g_wol[(size_t)HIDDEN * HIDDEN];
__device__ __nv_bfloat16 g_ah[(size_t)MROWS * HIDDEN];
__device__ __nv_bfloat16 g_al[(size_t)MROWS * HIDDEN];

// ---------------------------------------------------------------------------
// Helpers (base-ISA only: cp.async, ldmatrix, mma.sync — no 'a' features)
// ---------------------------------------------------------------------------
__device__ __forceinline__ uint32_t smem_u32(const void* p) {
    uint32_t a;
    asm("{ .reg .u64 t; cvta.to.shared.u64 t, %1; cvt.u32.u64 %0, t; }"
        : "=r"(a) : "l"(p));
    return a;
}

#define CP_ASYNC16(dst, src) \
    asm volatile("cp.async.cg.shared.global [%0], [%1], 16;\n" \
                 :: "r"(dst), "l"(src))
#define CP_COMMIT() asm volatile("cp.async.commit_group;\n" ::: "memory")
#define CP_WAIT0()  asm volatile("cp.async.wait_group 0;\n" ::: "memory")

__device__ __forceinline__ void ldsm4(uint32_t* r, uint32_t addr) {
    asm volatile("ldmatrix.sync.aligned.m8n8.x4.shared.b16 {%0,%1,%2,%3}, [%4];\n"
                 : "=r"(r[0]), "=r"(r[1]), "=r"(r[2]), "=r"(r[3]) : "r"(addr));
}

__device__ __forceinline__ void mma_bf16(float* d, const uint32_t* a, const uint32_t* b) {
    asm volatile("mma.sync.aligned.m16n8k16.row.col.f32.bf16.bf16.f32 "
                 "{%0,%1,%2,%3}, {%4,%5,%6,%7}, {%8,%9}, {%0,%1,%2,%3};\n"
                 : "+f"(d[0]), "+f"(d[1]), "+f"(d[2]), "+f"(d[3])
                 : "r"(a[0]), "r"(a[1]), "r"(a[2]), "r"(a[3]),
                   "r"(b[0]), "r"(b[1]));
}

// ---------------------------------------------------------------------------
// bf16-split GEMM via mma.sync: C[M,N] = (Ah+Al)[M,K] @ (Bh+Bl)[N,K]^T, fp32 C
// CTA tile 128x128, BK=32, 8 warps of 32x64, cp.async double-buffered.
// Smem rows padded to 40 bf16 (80B) for conflict-free ldmatrix.
// ---------------------------------------------------------------------------
#define SSTR 40
#define TILE_BYTES (128 * SSTR * 2)         // 10240
#define STAGE_BYTES (4 * TILE_BYTES)        // 40960
#define GEMM_SMEM (2 * STAGE_BYTES)         // 81920

__global__ __launch_bounds__(256, 1) void gemm_mma(
    const __nv_bfloat16* __restrict__ Ah, const __nv_bfloat16* __restrict__ Al,
    const __nv_bfloat16* __restrict__ Bh, const __nv_bfloat16* __restrict__ Bl,
    float* __restrict__ C, int Kdim, int Ndim)
{
    extern __shared__ char smem[];
    const uint32_t sbase = smem_u32(smem);
    const int tid = threadIdx.x;
    const int lane = tid & 31;
    const int wid = tid >> 5;
    const int warp_m = (wid >> 1) * 32;
    const int warp_n = (wid & 1) * 64;
    const int mt = blockIdx.x;
    const int nt = blockIdx.y;

    const __nv_bfloat16* gp[4];
    gp[0] = Ah + (size_t)mt * 128 * Kdim;
    gp[1] = Al + (size_t)mt * 128 * Kdim;
    gp[2] = Bh + (size_t)nt * 128 * Kdim;
    gp[3] = Bl + (size_t)nt * 128 * Kdim;

    const int NKC = Kdim >> 5;   // k-chunks of 32

    // stage loader: 4 tiles x 128 rows x 32 cols bf16
    const int lrow = tid >> 2;           // 0..63? no: seg below
    (void)lrow;

#define LOAD_STAGE(c, s) do { \
    const uint32_t sb_ = sbase + (s) * STAGE_BYTES; \
    _Pragma("unroll") \
    for (int t_ = 0; t_ < 4; t_++) { \
        _Pragma("unroll") \
        for (int i_ = 0; i_ < 2; i_++) { \
            const int seg_ = tid + i_ * 256;           /* 0..511 */ \
            const int r_ = seg_ >> 2;                  /* 0..127 */ \
            const int cs_ = (seg_ & 3) * 8;            /* 0,8,16,24 */ \
            const uint32_t dst_ = sb_ + t_ * TILE_BYTES + (r_ * SSTR + cs_) * 2; \
            const __nv_bfloat16* src_ = gp[t_] + (size_t)r_ * Kdim + (c) * 32 + cs_; \
            CP_ASYNC16(dst_, src_); \
        } \
    } \
} while (0)

    float acc[2][8][4];
#pragma unroll
    for (int mf = 0; mf < 2; mf++)
#pragma unroll
        for (int nf = 0; nf < 8; nf++)
#pragma unroll
            for (int e = 0; e < 4; e++) acc[mf][nf][e] = 0.f;

    LOAD_STAGE(0, 0);
    CP_COMMIT();

    const int arow = lane & 15;
    const int acolb = (lane >> 4) * 8;
    const int brow = (lane & 7) + ((lane >> 4) * 8);
    const int bcolb = ((lane >> 3) & 1) * 8;

    for (int c = 0; c < NKC; c++) {
        CP_WAIT0();
        __syncthreads();
        if (c + 1 < NKC) {
            LOAD_STAGE(c + 1, (c + 1) & 1);
            CP_COMMIT();
        }
        const uint32_t sb = sbase + (c & 1) * STAGE_BYTES;

#pragma unroll
        for (int kk = 0; kk < 2; kk++) {
            uint32_t a_h[2][4], a_l[2][4];
#pragma unroll
            for (int mf = 0; mf < 2; mf++) {
                const uint32_t ad = sb +
                    ((warp_m + mf * 16 + arow) * SSTR + acolb + kk * 16) * 2;
                ldsm4(a_h[mf], ad);
                ldsm4(a_l[mf], ad + TILE_BYTES);
            }
            uint32_t b_h[8][2], b_l[8][2];
#pragma unroll
            for (int np = 0; np < 4; np++) {
                const uint32_t bd = sb + 2 * TILE_BYTES +
                    ((warp_n + np * 16 + brow) * SSTR + bcolb + kk * 16) * 2;
                uint32_t r[4];
                ldsm4(r, bd);
                b_h[np * 2][0] = r[0]; b_h[np * 2][1] = r[1];
                b_h[np * 2 + 1][0] = r[2]; b_h[np * 2 + 1][1] = r[3];
                ldsm4(r, bd + TILE_BYTES);
                b_l[np * 2][0] = r[0]; b_l[np * 2][1] = r[1];
                b_l[np * 2 + 1][0] = r[2]; b_l[np * 2 + 1][1] = r[3];
            }
#pragma unroll
            for (int mf = 0; mf < 2; mf++)
#pragma unroll
                for (int nf = 0; nf < 8; nf++) {
                    mma_bf16(acc[mf][nf], a_h[mf], b_h[nf]);
                    mma_bf16(acc[mf][nf], a_h[mf], b_l[nf]);
                    mma_bf16(acc[mf][nf], a_l[mf], b_h[nf]);
                }
        }
        __syncthreads();
    }

    // Epilogue
    const int row_base = mt * 128 + warp_m + (lane >> 2);
    const int col_base = nt * 128 + warp_n + (lane & 3) * 2;
#pragma unroll
    for (int mf = 0; mf < 2; mf++)
#pragma unroll
        for (int nf = 0; nf < 8; nf++) {
            const int r0 = row_base + mf * 16;
            const int cc = col_base + nf * 8;
            *(float2*)(C + (size_t)r0 * Ndim + cc) =
                make_float2(acc[mf][nf][0], acc[mf][nf][1]);
            *(float2*)(C + (size_t)(r0 + 8) * Ndim + cc) =
                make_float2(acc[mf][nf][2], acc[mf][nf][3]);
        }
}

// ---------------------------------------------------------------------------
// fp32 -> bf16 hi/lo split (elementwise)
// ---------------------------------------------------------------------------
__global__ __launch_bounds__(256) void split_bf16(
    const float* __restrict__ in, __nv_bfloat16* __restrict__ hi,
    __nv_bfloat16* __restrict__ lo)
{
    const size_t i = (size_t)blockIdx.x * 256 + threadIdx.x;
    float4 v = *(const float4*)(in + i * 4);
    __nv_bfloat16 hx = __float2bfloat16(v.x);
    __nv_bfloat16 hy = __float2bfloat16(v.y);
    __nv_bfloat16 hz = __float2bfloat16(v.z);
    __nv_bfloat16 hw = __float2bfloat16(v.w);
    __nv_bfloat162* h2 = (__nv_bfloat162*)hi;
    __nv_bfloat162* l2 = (__nv_bfloat162*)lo;
    h2[i * 2 + 0] = __nv_bfloat162(hx, hy);
    h2[i * 2 + 1] = __nv_bfloat162(hz, hw);
    l2[i * 2 + 0] = __nv_bfloat162(__float2bfloat16(v.x - __bfloat162float(hx)),
                                   __float2bfloat16(v.y - __bfloat162float(hy)));
    l2[i * 2 + 1] = __nv_bfloat162(__float2bfloat16(v.z - __bfloat162float(hz)),
                                   __float2bfloat16(v.w - __bfloat162float(hw)));
}

// ---------------------------------------------------------------------------
// W[K,N] fp32 -> W^T[N,K] bf16 hi/lo
// ---------------------------------------------------------------------------
__global__ __launch_bounds__(256) void wsplit_T(
    const float* __restrict__ W, __nv_bfloat16* __restrict__ hiT,
    __nv_bfloat16* __restrict__ loT, int Kdim, int Ndim)
{
    __shared__ float sm[32][33];
    const int n0 = blockIdx.x * 32;
    const int k0 = blockIdx.y * 32;
    const int tx = threadIdx.x;
    const int ty = threadIdx.y;
#pragma unroll
    for (int j = 0; j < 4; j++) {
        const int r = ty + j * 8;
        sm[r][tx] = W[(size_t)(k0 + r) * Ndim + n0 + tx];
    }
    __syncthreads();
#pragma unroll
    for (int j = 0; j < 4; j++) {
        const int rt = ty + j * 8;
        const int n = n0 + rt;
        const int k = k0 + tx;
        const float v = sm[tx][rt];
        const __nv_bfloat16 h = __float2bfloat16(v);
        hiT[(size_t)n * Kdim + k] = h;
        loT[(size_t)n * Kdim + k] = __float2bfloat16(v - __bfloat162float(h));
    }
}

// ---------------------------------------------------------------------------
// RoPE + scatter
// ---------------------------------------------------------------------------
__global__ __launch_bounds__(256) void rope_scatter()
{
    const int idx = blockIdx.x * blockDim.x + threadIdx.x;
    const int d = idx & (HD - 1);
    const int l = (idx >> 7) & (LL - 1);
    const int h = (idx >> 18) & (NH - 1);
    const int b = idx >> 22;

    const float* row = g_qkv + (size_t)(b * LL + l) * QKVN;
    const float qv = row[h * HD + d];
    const float kv = row[NH * HD + h * HD + d];
    const float vv = row[2 * NH * HD + h * HD + d];

    const int dm = d & 63;
    const float inv = expf(-((float)(2 * dm) / 128.f) * 9.210340371976184f);
    const float ang = (float)l * inv;
    float s, c;
    sincosf(ang, &s, &c);

    const int p = (d < 64) ? d + 64 : d - 64;
    const float sgn = (d < 64) ? -1.f : 1.f;
    const float qp = row[h * HD + p];
    const float kp = row[NH * HD + h * HD + p];

    const float scale = 0.08838834764831845f;  // 1/sqrt(128)
    const size_t o = ((size_t)(b * NH + h) * LL + l) * HD + d;
    g_q[o] = (qv * c + sgn * qp * s) * scale;
    g_k[o] = kv * c + sgn * kp * s;
    g_v[o] = vv;
}

// ---------------------------------------------------------------------------
// Flash attention, fp32. BQ=BKV=64, D=128. 256 threads.
// ---------------------------------------------------------------------------
#define FLASH_SMEM ((128 * 64 + 128 * 64 + 64 * 128 + 64 * 65) * 4)

__global__ __launch_bounds__(256) void flash_attn_kernel(
    const float* __restrict__ Q, const float* __restrict__ K,
    const float* __restrict__ V, float* __restrict__ Out)
{
    extern __shared__ float fsm[];
    float* QT = fsm;
    float* KT = QT + 128 * 64;
    float* Vs = KT + 128 * 64;
    float* Ps = Vs + 64 * 128;

    const int tid = threadIdx.x;
    const int qt = blockIdx.x;
    const int bh = blockIdx.y;

    const float* Qg = Q + ((size_t)bh * LL + qt * 64) * HD;
    const float* Kg = K + (size_t)bh * LL * HD;
    const float* Vg = V + (size_t)bh * LL * HD;

    for (int idx = tid; idx < 64 * 128 / 4; idx += 256) {
        const int row = idx >> 5;
        const int d0 = (idx & 31) * 4;
        float4 v = *(const float4*)(Qg + (size_t)row * HD + d0);
        QT[(d0 + 0) * 64 + row] = v.x;
        QT[(d0 + 1) * 64 + row] = v.y;
        QT[(d0 + 2) * 64 + row] = v.z;
        QT[(d0 + 3) * 64 + row] = v.w;
    }

    const int ty = tid >> 4;
    const int tx = tid & 15;

    float acc[4][8];
    float m[4], l[4];
#pragma unroll
    for (int r = 0; r < 4; r++) {
        m[r] = NEGBIG; l[r] = 0.f;
#pragma unroll
        for (int c = 0; c < 8; c++) acc[r][c] = 0.f;
    }

    for (int kt = 0; kt <= qt; kt++) {
        const float* Kt = Kg + (size_t)kt * 64 * HD;
        const float* Vt = Vg + (size_t)kt * 64 * HD;

        __syncthreads();
        for (int idx = tid; idx < 64 * 128 / 4; idx += 256) {
            const int row = idx >> 5;
            const int d0 = (idx & 31) * 4;
            float4 v = *(const float4*)(Kt + (size_t)row * HD + d0);
            KT[(d0 + 0) * 64 + row] = v.x;
            KT[(d0 + 1) * 64 + row] = v.y;
            KT[(d0 + 2) * 64 + row] = v.z;
            KT[(d0 + 3) * 64 + row] = v.w;
            float4 w = *(const float4*)(Vt + (size_t)row * HD + d0);
            *(float4*)(Vs + (size_t)row * HD + d0) = w;
        }
        __syncthreads();

        float s[4][4];
#pragma unroll
        for (int r = 0; r < 4; r++)
#pragma unroll
            for (int c = 0; c < 4; c++) s[r][c] = 0.f;

        for (int d = 0; d < 128; d++) {
            float qa[4], kb[4];
            *(float4*)qa = *(float4*)&QT[d * 64 + ty * 4];
            *(float4*)kb = *(float4*)&KT[d * 64 + tx * 4];
#pragma unroll
            for (int r = 0; r < 4; r++)
#pragma unroll
                for (int c = 0; c < 4; c++)
                    s[r][c] += qa[r] * kb[c];
        }

        if (kt == qt) {
#pragma unroll
            for (int r = 0; r < 4; r++)
#pragma unroll
                for (int c = 0; c < 4; c++)
                    if (tx * 4 + c > ty * 4 + r) s[r][c] = NEGBIG;
        }

        float alpha[4];
#pragma unroll
        for (int r = 0; r < 4; r++) {
            float mx = s[r][0];
            mx = fmaxf(mx, s[r][1]); mx = fmaxf(mx, s[r][2]); mx = fmaxf(mx, s[r][3]);
#pragma unroll
            for (int off = 1; off < 16; off <<= 1)
                mx = fmaxf(mx, __shfl_xor_sync(0xFFFFFFFFu, mx, off));
            const float mn = fmaxf(m[r], mx);
            alpha[r] = __expf(m[r] - mn);
            m[r] = mn;
            float rs = 0.f;
#pragma unroll
            for (int c = 0; c < 4; c++) {
                s[r][c] = __expf(s[r][c] - mn);
                rs += s[r][c];
            }
#pragma unroll
            for (int off = 1; off < 16; off <<= 1)
                rs += __shfl_xor_sync(0xFFFFFFFFu, rs, off);
            l[r] = l[r] * alpha[r] + rs;
        }

#pragma unroll
        for (int r = 0; r < 4; r++)
#pragma unroll
            for (int c = 0; c < 4; c++)
                Ps[(ty * 4 + r) * 65 + tx * 4 + c] = s[r][c];
        __syncthreads();

#pragma unroll
        for (int r = 0; r < 4; r++)
#pragma unroll
            for (int c = 0; c < 8; c++)
                acc[r][c] *= alpha[r];

        for (int j = 0; j < 64; j++) {
            float p[4];
#pragma unroll
            for (int r = 0; r < 4; r++)
                p[r] = Ps[(ty * 4 + r) * 65 + j];
            float vv[8];
            *(float4*)(vv)     = *(float4*)&Vs[j * 128 + tx * 8];
            *(float4*)(vv + 4) = *(float4*)&Vs[j * 128 + tx * 8 + 4];
#pragma unroll
            for (int r = 0; r < 4; r++)
#pragma unroll
                for (int c = 0; c < 8; c++)
                    acc[r][c] += p[r] * vv[c];
        }
    }

    const int b = bh >> 4;
    const int h = bh & 15;
#pragma unroll
    for (int r = 0; r < 4; r++) {
        const float inv = 1.f / l[r];
        const int lrow = qt * 64 + ty * 4 + r;
        float* Og = Out + ((size_t)(b * LL + lrow)) * (NH * HD) + h * HD + tx * 8;
        float4 o0, o1;
        o0.x = acc[r][0] * inv; o0.y = acc[r][1] * inv;
        o0.z = acc[r][2] * inv; o0.w = acc[r][3] * inv;
        o1.x = acc[r][4] * inv; o1.y = acc[r][5] * inv;
        o1.z = acc[r][6] * inv; o1.w = acc[r][7] * inv;
        *(float4*)(Og)     = o0;
        *(float4*)(Og + 4) = o1;
    }
}

// ---------------------------------------------------------------------------
extern "C" void kernel_launch(void* const* d_in, const int* in_sizes, int n_in,
                              void* d_out, int out_size)
{
    const float* x    = (const float*)d_in[0];
    const float* Wqkv = (const float*)d_in[1];
    const float* Wo   = (const float*)d_in[2];
    float* out = (float*)d_out;

    float *qkv, *q, *k, *v, *attn;
    __nv_bfloat16 *xh, *xl, *wqh, *wql, *woh, *wol, *ah, *al;
    cudaGetSymbolAddress((void**)&qkv,  g_qkv);
    cudaGetSymbolAddress((void**)&q,    g_q);
    cudaGetSymbolAddress((void**)&k,    g_k);
    cudaGetSymbolAddress((void**)&v,    g_v);
    cudaGetSymbolAddress((void**)&attn, g_attn);
    cudaGetSymbolAddress((void**)&xh,   g_xh);
    cudaGetSymbolAddress((void**)&xl,   g_xl);
    cudaGetSymbolAddress((void**)&wqh,  g_wqh);
    cudaGetSymbolAddress((void**)&wql,  g_wql);
    cudaGetSymbolAddress((void**)&woh,  g_woh);
    cudaGetSymbolAddress((void**)&wol,  g_wol);
    cudaGetSymbolAddress((void**)&ah,   g_ah);
    cudaGetSymbolAddress((void**)&al,   g_al);

    cudaFuncSetAttribute(flash_attn_kernel,
                         cudaFuncAttributeMaxDynamicSharedMemorySize, FLASH_SMEM);
    cudaFuncSetAttribute(gemm_mma,
                         cudaFuncAttributeMaxDynamicSharedMemorySize, GEMM_SMEM);

    // Prep: split/transposed bf16 operands
    split_bf16<<<(MROWS * HIDDEN) / (256 * 4), 256>>>(x, xh, xl);
    wsplit_T<<<dim3(QKVN / 32, HIDDEN / 32), dim3(32, 8)>>>(Wqkv, wqh, wql, HIDDEN, QKVN);
    wsplit_T<<<dim3(HIDDEN / 32, HIDDEN / 32), dim3(32, 8)>>>(Wo, woh, wol, HIDDEN, HIDDEN);

    // 1) QKV projection (tensor cores via mma.sync)
    gemm_mma<<<dim3(MROWS / 128, QKVN / 128), 256, GEMM_SMEM>>>(
        xh, xl, wqh, wql, qkv, HIDDEN, QKVN);

    // 2) RoPE + scatter
    rope_scatter<<<(BB * NH * LL * HD) / 256, 256>>>();

    // 3) Causal flash attention (fp32)
    flash_attn_kernel<<<dim3(LL / 64, BB * NH), 256, FLASH_SMEM>>>(q, k, v, attn);

    // 4) Output projection (tensor cores via mma.sync)
    split_bf16<<<(MROWS * HIDDEN) / (256 * 4), 256>>>(attn, ah, al);
    gemm_mma<<<dim3(MROWS / 128, HIDDEN / 128), 256, GEMM_SMEM>>>(
        ah, al, woh, wol, out, HIDDEN, HIDDEN);
}

// round 5
// speedup vs baseline: 1.5813x; 1.0017x over previous
#include <cuda_runtime.h>
#include <cuda_bf16.h>
#include <stdint.h>
#include <math.h>

// Problem constants
#define BB 4
#define LL 2048
#define HIDDEN 2048
#define NH 16
#define HD 128
#define MROWS (BB * LL)          // 8192
#define QKVN (3 * NH * HD)       // 6144
#define NEGBIG -1e30f

// fp32 scratch
__device__ float g_qkv[(size_t)MROWS * QKVN];
__device__ float g_q[(size_t)BB * NH * LL * HD];
__device__ float g_k[(size_t)BB * NH * LL * HD];
__device__ float g_v[(size_t)BB * NH * LL * HD];
__device__ float g_attn[(size_t)MROWS * (NH * HD)];

// bf16 split operands
__device__ __nv_bfloat16 g_xh[(size_t)MROWS * HIDDEN];
__device__ __nv_bfloat16 g_xl[(size_t)MROWS * HIDDEN];
__device__ __nv_bfloat16 g_wqh[(size_t)QKVN * HIDDEN];   // Wqkv^T [6144,2048]
__device__ __nv_bfloat16 g_wql[(size_t)QKVN * HIDDEN];
__device__ __nv_bfloat16 g_woh[(size_t)HIDDEN * HIDDEN]; // Wo^T [2048,2048]
__device__ __nv_bfloat16 g_wol[(size_t)HIDDEN * HIDDEN];
__device__ __nv_bfloat16 g_ah[(size_t)MROWS * HIDDEN];
__device__ __nv_bfloat16 g_al[(size_t)MROWS * HIDDEN];

// ---------------------------------------------------------------------------
// Helpers (base-ISA only: cp.async, ldmatrix, mma.sync — no 'a' features)
// ---------------------------------------------------------------------------
__device__ __forceinline__ uint32_t smem_u32(const void* p) {
    uint32_t a;
    asm("{ .reg .u64 t; cvta.to.shared.u64 t, %1; cvt.u32.u64 %0, t; }"
        : "=r"(a) : "l"(p));
    return a;
}

#define CP_ASYNC16(dst, src) \
    asm volatile("cp.async.cg.shared.global [%0], [%1], 16;\n" \
                 :: "r"(dst), "l"(src))
#define CP_COMMIT() asm volatile("cp.async.commit_group;\n" ::: "memory")
#define CP_WAIT0()  asm volatile("cp.async.wait_group 0;\n" ::: "memory")

__device__ __forceinline__ void ldsm4(uint32_t* r, uint32_t addr) {
    asm volatile("ldmatrix.sync.aligned.m8n8.x4.shared.b16 {%0,%1,%2,%3}, [%4];\n"
                 : "=r"(r[0]), "=r"(r[1]), "=r"(r[2]), "=r"(r[3]) : "r"(addr));
}

__device__ __forceinline__ void mma_bf16(float* d, const uint32_t* a, const uint32_t* b) {
    asm volatile("mma.sync.aligned.m16n8k16.row.col.f32.bf16.bf16.f32 "
                 "{%0,%1,%2,%3}, {%4,%5,%6,%7}, {%8,%9}, {%0,%1,%2,%3};\n"
                 : "+f"(d[0]), "+f"(d[1]), "+f"(d[2]), "+f"(d[3])
                 : "r"(a[0]), "r"(a[1]), "r"(a[2]), "r"(a[3]),
                   "r"(b[0]), "r"(b[1]));
}

// ---------------------------------------------------------------------------
// bf16-split GEMM via mma.sync: C[M,N] = (Ah+Al)[M,K] @ (Bh+Bl)[N,K]^T, fp32 C
// CTA tile 128x128, BK=32, 8 warps of 32x64, cp.async double-buffered.
// Smem rows padded to 40 bf16 (80B) for conflict-free ldmatrix.
// ---------------------------------------------------------------------------
#define SSTR 40
#define TILE_BYTES (128 * SSTR * 2)         // 10240
#define STAGE_BYTES (4 * TILE_BYTES)        // 40960
#define GEMM_SMEM (2 * STAGE_BYTES)         // 81920

__global__ __launch_bounds__(256, 1) void gemm_mma(
    const __nv_bfloat16* __restrict__ Ah, const __nv_bfloat16* __restrict__ Al,
    const __nv_bfloat16* __restrict__ Bh, const __nv_bfloat16* __restrict__ Bl,
    float* __restrict__ C, int Kdim, int Ndim)
{
    extern __shared__ char smem[];
    const uint32_t sbase = smem_u32(smem);
    const int tid = threadIdx.x;
    const int lane = tid & 31;
    const int wid = tid >> 5;
    const int warp_m = (wid >> 1) * 32;
    const int warp_n = (wid & 1) * 64;
    const int mt = blockIdx.x;
    const int nt = blockIdx.y;

    const __nv_bfloat16* gp[4];
    gp[0] = Ah + (size_t)mt * 128 * Kdim;
    gp[1] = Al + (size_t)mt * 128 * Kdim;
    gp[2] = Bh + (size_t)nt * 128 * Kdim;
    gp[3] = Bl + (size_t)nt * 128 * Kdim;

    const int NKC = Kdim >> 5;   // k-chunks of 32

    // stage loader: 4 tiles x 128 rows x 32 cols bf16
    const int lrow = tid >> 2;           // 0..63? no: seg below
    (void)lrow;

#define LOAD_STAGE(c, s) do { \
    const uint32_t sb_ = sbase + (s) * STAGE_BYTES; \
    _Pragma("unroll") \
    for (int t_ = 0; t_ < 4; t_++) { \
        _Pragma("unroll") \
        for (int i_ = 0; i_ < 2; i_++) { \
            const int seg_ = tid + i_ * 256;           /* 0..511 */ \
            const int r_ = seg_ >> 2;                  /* 0..127 */ \
            const int cs_ = (seg_ & 3) * 8;            /* 0,8,16,24 */ \
            const uint32_t dst_ = sb_ + t_ * TILE_BYTES + (r_ * SSTR + cs_) * 2; \
            const __nv_bfloat16* src_ = gp[t_] + (size_t)r_ * Kdim + (c) * 32 + cs_; \
            CP_ASYNC16(dst_, src_); \
        } \
    } \
} while (0)

    float acc[2][8][4];
#pragma unroll
    for (int mf = 0; mf < 2; mf++)
#pragma unroll
        for (int nf = 0; nf < 8; nf++)
#pragma unroll
            for (int e = 0; e < 4; e++) acc[mf][nf][e] = 0.f;

    LOAD_STAGE(0, 0);
    CP_COMMIT();

    const int arow = lane & 15;
    const int acolb = (lane >> 4) * 8;
    const int brow = (lane & 7) + ((lane >> 4) * 8);
    const int bcolb = ((lane >> 3) & 1) * 8;

    for (int c = 0; c < NKC; c++) {
        CP_WAIT0();
        __syncthreads();
        if (c + 1 < NKC) {
            LOAD_STAGE(c + 1, (c + 1) & 1);
            CP_COMMIT();
        }
        const uint32_t sb = sbase + (c & 1) * STAGE_BYTES;

#pragma unroll
        for (int kk = 0; kk < 2; kk++) {
            uint32_t a_h[2][4], a_l[2][4];
#pragma unroll
            for (int mf = 0; mf < 2; mf++) {
                const uint32_t ad = sb +
                    ((warp_m + mf * 16 + arow) * SSTR + acolb + kk * 16) * 2;
                ldsm4(a_h[mf], ad);
                ldsm4(a_l[mf], ad + TILE_BYTES);
            }
            uint32_t b_h[8][2], b_l[8][2];
#pragma unroll
            for (int np = 0; np < 4; np++) {
                const uint32_t bd = sb + 2 * TILE_BYTES +
                    ((warp_n + np * 16 + brow) * SSTR + bcolb + kk * 16) * 2;
                uint32_t r[4];
                ldsm4(r, bd);
                b_h[np * 2][0] = r[0]; b_h[np * 2][1] = r[1];
                b_h[np * 2 + 1][0] = r[2]; b_h[np * 2 + 1][1] = r[3];
                ldsm4(r, bd + TILE_BYTES);
                b_l[np * 2][0] = r[0]; b_l[np * 2][1] = r[1];
                b_l[np * 2 + 1][0] = r[2]; b_l[np * 2 + 1][1] = r[3];
            }
#pragma unroll
            for (int mf = 0; mf < 2; mf++)
#pragma unroll
                for (int nf = 0; nf < 8; nf++) {
                    mma_bf16(acc[mf][nf], a_h[mf], b_h[nf]);
                    mma_bf16(acc[mf][nf], a_h[mf], b_l[nf]);
                    mma_bf16(acc[mf][nf], a_l[mf], b_h[nf]);
                }
        }
        __syncthreads();
    }

    // Epilogue
    const int row_base = mt * 128 + warp_m + (lane >> 2);
    const int col_base = nt * 128 + warp_n + (lane & 3) * 2;
#pragma unroll
    for (int mf = 0; mf < 2; mf++)
#pragma unroll
        for (int nf = 0; nf < 8; nf++) {
            const int r0 = row_base + mf * 16;
            const int cc = col_base + nf * 8;
            *(float2*)(C + (size_t)r0 * Ndim + cc) =
                make_float2(acc[mf][nf][0], acc[mf][nf][1]);
            *(float2*)(C + (size_t)(r0 + 8) * Ndim + cc) =
                make_float2(acc[mf][nf][2], acc[mf][nf][3]);
        }
}

// ---------------------------------------------------------------------------
// fp32 -> bf16 hi/lo split (elementwise)
// ---------------------------------------------------------------------------
__global__ __launch_bounds__(256) void split_bf16(
    const float* __restrict__ in, __nv_bfloat16* __restrict__ hi,
    __nv_bfloat16* __restrict__ lo)
{
    const size_t i = (size_t)blockIdx.x * 256 + threadIdx.x;
    float4 v = *(const float4*)(in + i * 4);
    __nv_bfloat16 hx = __float2bfloat16(v.x);
    __nv_bfloat16 hy = __float2bfloat16(v.y);
    __nv_bfloat16 hz = __float2bfloat16(v.z);
    __nv_bfloat16 hw = __float2bfloat16(v.w);
    __nv_bfloat162* h2 = (__nv_bfloat162*)hi;
    __nv_bfloat162* l2 = (__nv_bfloat162*)lo;
    h2[i * 2 + 0] = __nv_bfloat162(hx, hy);
    h2[i * 2 + 1] = __nv_bfloat162(hz, hw);
    l2[i * 2 + 0] = __nv_bfloat162(__float2bfloat16(v.x - __bfloat162float(hx)),
                                   __float2bfloat16(v.y - __bfloat162float(hy)));
    l2[i * 2 + 1] = __nv_bfloat162(__float2bfloat16(v.z - __bfloat162float(hz)),
                                   __float2bfloat16(v.w - __bfloat162float(hw)));
}

// ---------------------------------------------------------------------------
// W[K,N] fp32 -> W^T[N,K] bf16 hi/lo
// ---------------------------------------------------------------------------
__global__ __launch_bounds__(256) void wsplit_T(
    const float* __restrict__ W, __nv_bfloat16* __restrict__ hiT,
    __nv_bfloat16* __restrict__ loT, int Kdim, int Ndim)
{
    __shared__ float sm[32][33];
    const int n0 = blockIdx.x * 32;
    const int k0 = blockIdx.y * 32;
    const int tx = threadIdx.x;
    const int ty = threadIdx.y;
#pragma unroll
    for (int j = 0; j < 4; j++) {
        const int r = ty + j * 8;
        sm[r][tx] = W[(size_t)(k0 + r) * Ndim + n0 + tx];
    }
    __syncthreads();
#pragma unroll
    for (int j = 0; j < 4; j++) {
        const int rt = ty + j * 8;
        const int n = n0 + rt;
        const int k = k0 + tx;
        const float v = sm[tx][rt];
        const __nv_bfloat16 h = __float2bfloat16(v);
        hiT[(size_t)n * Kdim + k] = h;
        loT[(size_t)n * Kdim + k] = __float2bfloat16(v - __bfloat162float(h));
    }
}

// ---------------------------------------------------------------------------
// RoPE + scatter
// ---------------------------------------------------------------------------
__global__ __launch_bounds__(256) void rope_scatter()
{
    const int idx = blockIdx.x * blockDim.x + threadIdx.x;
    const int d = idx & (HD - 1);
    const int l = (idx >> 7) & (LL - 1);
    const int h = (idx >> 18) & (NH - 1);
    const int b = idx >> 22;

    const float* row = g_qkv + (size_t)(b * LL + l) * QKVN;
    const float qv = row[h * HD + d];
    const float kv = row[NH * HD + h * HD + d];
    const float vv = row[2 * NH * HD + h * HD + d];

    const int dm = d & 63;
    const float inv = expf(-((float)(2 * dm) / 128.f) * 9.210340371976184f);
    const float ang = (float)l * inv;
    float s, c;
    sincosf(ang, &s, &c);

    const int p = (d < 64) ? d + 64 : d - 64;
    const float sgn = (d < 64) ? -1.f : 1.f;
    const float qp = row[h * HD + p];
    const float kp = row[NH * HD + h * HD + p];

    const float scale = 0.08838834764831845f;  // 1/sqrt(128)
    const size_t o = ((size_t)(b * NH + h) * LL + l) * HD + d;
    g_q[o] = (qv * c + sgn * qp * s) * scale;
    g_k[o] = kv * c + sgn * kp * s;
    g_v[o] = vv;
}

// ---------------------------------------------------------------------------
// Flash attention, fp32. BQ=BKV=64, D=128. 256 threads.
// ---------------------------------------------------------------------------
#define FLASH_SMEM ((128 * 64 + 128 * 64 + 64 * 128 + 64 * 65) * 4)

__global__ __launch_bounds__(256) void flash_attn_kernel(
    const float* __restrict__ Q, const float* __restrict__ K,
    const float* __restrict__ V, float* __restrict__ Out)
{
    extern __shared__ float fsm[];
    float* QT = fsm;
    float* KT = QT + 128 * 64;
    float* Vs = KT + 128 * 64;
    float* Ps = Vs + 64 * 128;

    const int tid = threadIdx.x;
    const int qt = blockIdx.x;
    const int bh = blockIdx.y;

    const float* Qg = Q + ((size_t)bh * LL + qt * 64) * HD;
    const float* Kg = K + (size_t)bh * LL * HD;
    const float* Vg = V + (size_t)bh * LL * HD;

    for (int idx = tid; idx < 64 * 128 / 4; idx += 256) {
        const int row = idx >> 5;
        const int d0 = (idx & 31) * 4;
        float4 v = *(const float4*)(Qg + (size_t)row * HD + d0);
        QT[(d0 + 0) * 64 + row] = v.x;
        QT[(d0 + 1) * 64 + row] = v.y;
        QT[(d0 + 2) * 64 + row] = v.z;
        QT[(d0 + 3) * 64 + row] = v.w;
    }

    const int ty = tid >> 4;
    const int tx = tid & 15;

    float acc[4][8];
    float m[4], l[4];
#pragma unroll
    for (int r = 0; r < 4; r++) {
        m[r] = NEGBIG; l[r] = 0.f;
#pragma unroll
        for (int c = 0; c < 8; c++) acc[r][c] = 0.f;
    }

    for (int kt = 0; kt <= qt; kt++) {
        const float* Kt = Kg + (size_t)kt * 64 * HD;
        const float* Vt = Vg + (size_t)kt * 64 * HD;

        __syncthreads();
        for (int idx = tid; idx < 64 * 128 / 4; idx += 256) {
            const int row = idx >> 5;
            const int d0 = (idx & 31) * 4;
            float4 v = *(const float4*)(Kt + (size_t)row * HD + d0);
            KT[(d0 + 0) * 64 + row] = v.x;
            KT[(d0 + 1) * 64 + row] = v.y;
            KT[(d0 + 2) * 64 + row] = v.z;
            KT[(d0 + 3) * 64 + row] = v.w;
            float4 w = *(const float4*)(Vt + (size_t)row * HD + d0);
            *(float4*)(Vs + (size_t)row * HD + d0) = w;
        }
        __syncthreads();

        float s[4][4];
#pragma unroll
        for (int r = 0; r < 4; r++)
#pragma unroll
            for (int c = 0; c < 4; c++) s[r][c] = 0.f;

        for (int d = 0; d < 128; d++) {
            float qa[4], kb[4];
            *(float4*)qa = *(float4*)&QT[d * 64 + ty * 4];
            *(float4*)kb = *(float4*)&KT[d * 64 + tx * 4];
#pragma unroll
            for (int r = 0; r < 4; r++)
#pragma unroll
                for (int c = 0; c < 4; c++)
                    s[r][c] += qa[r] * kb[c];
        }

        if (kt == qt) {
#pragma unroll
            for (int r = 0; r < 4; r++)
#pragma unroll
                for (int c = 0; c < 4; c++)
                    if (tx * 4 + c > ty * 4 + r) s[r][c] = NEGBIG;
        }

        float alpha[4];
#pragma unroll
        for (int r = 0; r < 4; r++) {
            float mx = s[r][0];
            mx = fmaxf(mx, s[r][1]); mx = fmaxf(mx, s[r][2]); mx = fmaxf(mx, s[r][3]);
#pragma unroll
            for (int off = 1; off < 16; off <<= 1)
                mx = fmaxf(mx, __shfl_xor_sync(0xFFFFFFFFu, mx, off));
            const float mn = fmaxf(m[r], mx);
            alpha[r] = __expf(m[r] - mn);
            m[r] = mn;
            float rs = 0.f;
#pragma unroll
            for (int c = 0; c < 4; c++) {
                s[r][c] = __expf(s[r][c] - mn);
                rs += s[r][c];
            }
#pragma unroll
            for (int off = 1; off < 16; off <<= 1)
                rs += __shfl_xor_sync(0xFFFFFFFFu, rs, off);
            l[r] = l[r] * alpha[r] + rs;
        }

#pragma unroll
        for (int r = 0; r < 4; r++)
#pragma unroll
            for (int c = 0; c < 4; c++)
                Ps[(ty * 4 + r) * 65 + tx * 4 + c] = s[r][c];
        __syncthreads();

#pragma unroll
        for (int r = 0; r < 4; r++)
#pragma unroll
            for (int c = 0; c < 8; c++)
                acc[r][c] *= alpha[r];

        for (int j = 0; j < 64; j++) {
            float p[4];
#pragma unroll
            for (int r = 0; r < 4; r++)
                p[r] = Ps[(ty * 4 + r) * 65 + j];
            float vv[8];
            *(float4*)(vv)     = *(float4*)&Vs[j * 128 + tx * 8];
            *(float4*)(vv + 4) = *(float4*)&Vs[j * 128 + tx * 8 + 4];
#pragma unroll
            for (int r = 0; r < 4; r++)
#pragma unroll
                for (int c = 0; c < 8; c++)
                    acc[r][c] += p[r] * vv[c];
        }
    }

    const int b = bh >> 4;
    const int h = bh & 15;
#pragma unroll
    for (int r = 0; r < 4; r++) {
        const float inv = 1.f / l[r];
        const int lrow = qt * 64 + ty * 4 + r;
        float* Og = Out + ((size_t)(b * LL + lrow)) * (NH * HD) + h * HD + tx * 8;
        float4 o0, o1;
        o0.x = acc[r][0] * inv; o0.y = acc[r][1] * inv;
        o0.z = acc[r][2] * inv; o0.w = acc[r][3] * inv;
        o1.x = acc[r][4] * inv; o1.y = acc[r][5] * inv;
        o1.z = acc[r][6] * inv; o1.w = acc[r][7] * inv;
        *(float4*)(Og)     = o0;
        *(float4*)(Og + 4) = o1;
    }
}

// ---------------------------------------------------------------------------
extern "C" void kernel_launch(void* const* d_in, const int* in_sizes, int n_in,
                              void* d_out, int out_size)
{
    const float* x    = (const float*)d_in[0];
    const float* Wqkv = (const float*)d_in[1];
    const float* Wo   = (const float*)d_in[2];
    float* out = (float*)d_out;

    float *qkv, *q, *k, *v, *attn;
    __nv_bfloat16 *xh, *xl, *wqh, *wql, *woh, *wol, *ah, *al;
    cudaGetSymbolAddress((void**)&qkv,  g_qkv);
    cudaGetSymbolAddress((void**)&q,    g_q);
    cudaGetSymbolAddress((void**)&k,    g_k);
    cudaGetSymbolAddress((void**)&v,    g_v);
    cudaGetSymbolAddress((void**)&attn, g_attn);
    cudaGetSymbolAddress((void**)&xh,   g_xh);
    cudaGetSymbolAddress((void**)&xl,   g_xl);
    cudaGetSymbolAddress((void**)&wqh,  g_wqh);
    cudaGetSymbolAddress((void**)&wql,  g_wql);
    cudaGetSymbolAddress((void**)&woh,  g_woh);
    cudaGetSymbolAddress((void**)&wol,  g_wol);
    cudaGetSymbolAddress((void**)&ah,   g_ah);
    cudaGetSymbolAddress((void**)&al,   g_al);

    cudaFuncSetAttribute(flash_attn_kernel,
                         cudaFuncAttributeMaxDynamicSharedMemorySize, FLASH_SMEM);
    cudaFuncSetAttribute(gemm_mma,
                         cudaFuncAttributeMaxDynamicSharedMemorySize, GEMM_SMEM);

    // Prep: split/transposed bf16 operands
    split_bf16<<<(MROWS * HIDDEN) / (256 * 4), 256>>>(x, xh, xl);
    wsplit_T<<<dim3(QKVN / 32, HIDDEN / 32), dim3(32, 8)>>>(Wqkv, wqh, wql, HIDDEN, QKVN);
    wsplit_T<<<dim3(HIDDEN / 32, HIDDEN / 32), dim3(32, 8)>>>(Wo, woh, wol, HIDDEN, HIDDEN);

    // 1) QKV projection (tensor cores via mma.sync)
    gemm_mma<<<dim3(MROWS / 128, QKVN / 128), 256, GEMM_SMEM>>>(
        xh, xl, wqh, wql, qkv, HIDDEN, QKVN);

    // 2) RoPE + scatter
    rope_scatter<<<(BB * NH * LL * HD) / 256, 256>>>();

    // 3) Causal flash attention (fp32)
    flash_attn_kernel<<<dim3(LL / 64, BB * NH), 256, FLASH_SMEM>>>(q, k, v, attn);

    // 4) Output projection (tensor cores via mma.sync)
    split_bf16<<<(MROWS * HIDDEN) / (256 * 4), 256>>>(attn, ah, al);
    gemm_mma<<<dim3(MROWS / 128, HIDDEN / 128), 256, GEMM_SMEM>>>(
        ah, al, woh, wol, out, HIDDEN, HIDDEN);
}

// round 6
// speedup vs baseline: 2.8803x; 1.8215x over previous
#include <cuda_runtime.h>
#include <cuda_bf16.h>
#include <stdint.h>
#include <math.h>

// Problem constants
#define BB 4
#define LL 2048
#define HIDDEN 2048
#define NH 16
#define HD 128
#define MROWS (BB * LL)          // 8192
#define QKVN (3 * NH * HD)       // 6144
#define NEGBIG -1e30f

// Scratch
__device__ float g_qkv[(size_t)MROWS * QKVN];

__device__ __nv_bfloat16 g_xh[(size_t)MROWS * HIDDEN];
__device__ __nv_bfloat16 g_xl[(size_t)MROWS * HIDDEN];
__device__ __nv_bfloat16 g_wqh[(size_t)QKVN * HIDDEN];   // Wqkv^T
__device__ __nv_bfloat16 g_wql[(size_t)QKVN * HIDDEN];
__device__ __nv_bfloat16 g_woh[(size_t)HIDDEN * HIDDEN]; // Wo^T
__device__ __nv_bfloat16 g_wol[(size_t)HIDDEN * HIDDEN];
__device__ __nv_bfloat16 g_ah[(size_t)MROWS * HIDDEN];   // attention out hi/lo
__device__ __nv_bfloat16 g_al[(size_t)MROWS * HIDDEN];

// Q/K/V bf16 hi/lo, layout [b,h,l,d]
#define QKV_ELEMS ((size_t)BB * NH * LL * HD)
__device__ __nv_bfloat16 g_qh_a[QKV_ELEMS];
__device__ __nv_bfloat16 g_ql_a[QKV_ELEMS];
__device__ __nv_bfloat16 g_kh_a[QKV_ELEMS];
__device__ __nv_bfloat16 g_kl_a[QKV_ELEMS];
__device__ __nv_bfloat16 g_vh_a[QKV_ELEMS];
__device__ __nv_bfloat16 g_vl_a[QKV_ELEMS];

// ---------------------------------------------------------------------------
// Helpers (base ISA: cp.async, ldmatrix, mma.sync)
// ---------------------------------------------------------------------------
__device__ __forceinline__ uint32_t smem_u32(const void* p) {
    uint32_t a;
    asm("{ .reg .u64 t; cvta.to.shared.u64 t, %1; cvt.u32.u64 %0, t; }"
        : "=r"(a) : "l"(p));
    return a;
}

#define CP_ASYNC16(dst, src) \
    asm volatile("cp.async.cg.shared.global [%0], [%1], 16;\n" \
                 :: "r"(dst), "l"(src))
#define CP_COMMIT() asm volatile("cp.async.commit_group;\n" ::: "memory")
#define CP_WAIT0()  asm volatile("cp.async.wait_group 0;\n" ::: "memory")
#define CP_WAIT1()  asm volatile("cp.async.wait_group 1;\n" ::: "memory")

__device__ __forceinline__ void ldsm4(uint32_t* r, uint32_t addr) {
    asm volatile("ldmatrix.sync.aligned.m8n8.x4.shared.b16 {%0,%1,%2,%3}, [%4];\n"
                 : "=r"(r[0]), "=r"(r[1]), "=r"(r[2]), "=r"(r[3]) : "r"(addr));
}
__device__ __forceinline__ void ldsm4t(uint32_t* r, uint32_t addr) {
    asm volatile("ldmatrix.sync.aligned.m8n8.x4.trans.shared.b16 {%0,%1,%2,%3}, [%4];\n"
                 : "=r"(r[0]), "=r"(r[1]), "=r"(r[2]), "=r"(r[3]) : "r"(addr));
}

__device__ __forceinline__ void mma_bf16(float* d, const uint32_t* a, const uint32_t* b) {
    asm volatile("mma.sync.aligned.m16n8k16.row.col.f32.bf16.bf16.f32 "
                 "{%0,%1,%2,%3}, {%4,%5,%6,%7}, {%8,%9}, {%0,%1,%2,%3};\n"
                 : "+f"(d[0]), "+f"(d[1]), "+f"(d[2]), "+f"(d[3])
                 : "r"(a[0]), "r"(a[1]), "r"(a[2]), "r"(a[3]),
                   "r"(b[0]), "r"(b[1]));
}

__device__ __forceinline__ uint32_t pack_bf16(float a, float b) {
    __nv_bfloat162 t = __floats2bfloat162_rn(a, b);
    return *(uint32_t*)&t;
}
__device__ __forceinline__ float bf16_res(float a) {
    return a - __bfloat162float(__float2bfloat16(a));
}

// ---------------------------------------------------------------------------
// bf16-split GEMM via mma.sync (verified in R5)
// ---------------------------------------------------------------------------
#define SSTR 40
#define TILE_BYTES (128 * SSTR * 2)         // 10240
#define STAGE_BYTES (4 * TILE_BYTES)        // 40960
#define GEMM_SMEM (2 * STAGE_BYTES)         // 81920

__global__ __launch_bounds__(256, 1) void gemm_mma(
    const __nv_bfloat16* __restrict__ Ah, const __nv_bfloat16* __restrict__ Al,
    const __nv_bfloat16* __restrict__ Bh, const __nv_bfloat16* __restrict__ Bl,
    float* __restrict__ C, int Kdim, int Ndim)
{
    extern __shared__ char smem[];
    const uint32_t sbase = smem_u32(smem);
    const int tid = threadIdx.x;
    const int lane = tid & 31;
    const int wid = tid >> 5;
    const int warp_m = (wid >> 1) * 32;
    const int warp_n = (wid & 1) * 64;
    const int mt = blockIdx.x;
    const int nt = blockIdx.y;

    const __nv_bfloat16* gp[4];
    gp[0] = Ah + (size_t)mt * 128 * Kdim;
    gp[1] = Al + (size_t)mt * 128 * Kdim;
    gp[2] = Bh + (size_t)nt * 128 * Kdim;
    gp[3] = Bl + (size_t)nt * 128 * Kdim;

    const int NKC = Kdim >> 5;

#define LOAD_STAGE(c, s) do { \
    const uint32_t sb_ = sbase + (s) * STAGE_BYTES; \
    _Pragma("unroll") \
    for (int t_ = 0; t_ < 4; t_++) { \
        _Pragma("unroll") \
        for (int i_ = 0; i_ < 2; i_++) { \
            const int seg_ = tid + i_ * 256; \
            const int r_ = seg_ >> 2; \
            const int cs_ = (seg_ & 3) * 8; \
            const uint32_t dst_ = sb_ + t_ * TILE_BYTES + (r_ * SSTR + cs_) * 2; \
            const __nv_bfloat16* src_ = gp[t_] + (size_t)r_ * Kdim + (c) * 32 + cs_; \
            CP_ASYNC16(dst_, src_); \
        } \
    } \
} while (0)

    float acc[2][8][4];
#pragma unroll
    for (int mf = 0; mf < 2; mf++)
#pragma unroll
        for (int nf = 0; nf < 8; nf++)
#pragma unroll
            for (int e = 0; e < 4; e++) acc[mf][nf][e] = 0.f;

    LOAD_STAGE(0, 0);
    CP_COMMIT();

    const int arow = lane & 15;
    const int acolb = (lane >> 4) * 8;
    const int brow = (lane & 7) + ((lane >> 4) * 8);
    const int bcolb = ((lane >> 3) & 1) * 8;

    for (int c = 0; c < NKC; c++) {
        CP_WAIT0();
        __syncthreads();
        if (c + 1 < NKC) {
            LOAD_STAGE(c + 1, (c + 1) & 1);
            CP_COMMIT();
        }
        const uint32_t sb = sbase + (c & 1) * STAGE_BYTES;

#pragma unroll
        for (int kk = 0; kk < 2; kk++) {
            uint32_t a_h[2][4], a_l[2][4];
#pragma unroll
            for (int mf = 0; mf < 2; mf++) {
                const uint32_t ad = sb +
                    ((warp_m + mf * 16 + arow) * SSTR + acolb + kk * 16) * 2;
                ldsm4(a_h[mf], ad);
                ldsm4(a_l[mf], ad + TILE_BYTES);
            }
            uint32_t b_h[8][2], b_l[8][2];
#pragma unroll
            for (int np = 0; np < 4; np++) {
                const uint32_t bd = sb + 2 * TILE_BYTES +
                    ((warp_n + np * 16 + brow) * SSTR + bcolb + kk * 16) * 2;
                uint32_t r[4];
                ldsm4(r, bd);
                b_h[np * 2][0] = r[0]; b_h[np * 2][1] = r[1];
                b_h[np * 2 + 1][0] = r[2]; b_h[np * 2 + 1][1] = r[3];
                ldsm4(r, bd + TILE_BYTES);
                b_l[np * 2][0] = r[0]; b_l[np * 2][1] = r[1];
                b_l[np * 2 + 1][0] = r[2]; b_l[np * 2 + 1][1] = r[3];
            }
#pragma unroll
            for (int mf = 0; mf < 2; mf++)
#pragma unroll
                for (int nf = 0; nf < 8; nf++) {
                    mma_bf16(acc[mf][nf], a_h[mf], b_h[nf]);
                    mma_bf16(acc[mf][nf], a_h[mf], b_l[nf]);
                    mma_bf16(acc[mf][nf], a_l[mf], b_h[nf]);
                }
        }
        __syncthreads();
    }

    const int row_base = mt * 128 + warp_m + (lane >> 2);
    const int col_base = nt * 128 + warp_n + (lane & 3) * 2;
#pragma unroll
    for (int mf = 0; mf < 2; mf++)
#pragma unroll
        for (int nf = 0; nf < 8; nf++) {
            const int r0 = row_base + mf * 16;
            const int cc = col_base + nf * 8;
            *(float2*)(C + (size_t)r0 * Ndim + cc) =
                make_float2(acc[mf][nf][0], acc[mf][nf][1]);
            *(float2*)(C + (size_t)(r0 + 8) * Ndim + cc) =
                make_float2(acc[mf][nf][2], acc[mf][nf][3]);
        }
}

// ---------------------------------------------------------------------------
// fp32 -> bf16 hi/lo split (elementwise)
// ---------------------------------------------------------------------------
__global__ __launch_bounds__(256) void split_bf16(
    const float* __restrict__ in, __nv_bfloat16* __restrict__ hi,
    __nv_bfloat16* __restrict__ lo)
{
    const size_t i = (size_t)blockIdx.x * 256 + threadIdx.x;
    float4 v = *(const float4*)(in + i * 4);
    __nv_bfloat16 hx = __float2bfloat16(v.x);
    __nv_bfloat16 hy = __float2bfloat16(v.y);
    __nv_bfloat16 hz = __float2bfloat16(v.z);
    __nv_bfloat16 hw = __float2bfloat16(v.w);
    __nv_bfloat162* h2 = (__nv_bfloat162*)hi;
    __nv_bfloat162* l2 = (__nv_bfloat162*)lo;
    h2[i * 2 + 0] = __nv_bfloat162(hx, hy);
    h2[i * 2 + 1] = __nv_bfloat162(hz, hw);
    l2[i * 2 + 0] = __nv_bfloat162(__float2bfloat16(v.x - __bfloat162float(hx)),
                                   __float2bfloat16(v.y - __bfloat162float(hy)));
    l2[i * 2 + 1] = __nv_bfloat162(__float2bfloat16(v.z - __bfloat162float(hz)),
                                   __float2bfloat16(v.w - __bfloat162float(hw)));
}

// ---------------------------------------------------------------------------
// W[K,N] fp32 -> W^T[N,K] bf16 hi/lo
// ---------------------------------------------------------------------------
__global__ __launch_bounds__(256) void wsplit_T(
    const float* __restrict__ W, __nv_bfloat16* __restrict__ hiT,
    __nv_bfloat16* __restrict__ loT, int Kdim, int Ndim)
{
    __shared__ float sm[32][33];
    const int n0 = blockIdx.x * 32;
    const int k0 = blockIdx.y * 32;
    const int tx = threadIdx.x;
    const int ty = threadIdx.y;
#pragma unroll
    for (int j = 0; j < 4; j++) {
        const int r = ty + j * 8;
        sm[r][tx] = W[(size_t)(k0 + r) * Ndim + n0 + tx];
    }
    __syncthreads();
#pragma unroll
    for (int j = 0; j < 4; j++) {
        const int rt = ty + j * 8;
        const int n = n0 + rt;
        const int k = k0 + tx;
        const float v = sm[tx][rt];
        const __nv_bfloat16 h = __float2bfloat16(v);
        hiT[(size_t)n * Kdim + k] = h;
        loT[(size_t)n * Kdim + k] = __float2bfloat16(v - __bfloat162float(h));
    }
}

// ---------------------------------------------------------------------------
// RoPE + scatter to bf16 hi/lo [b,h,l,d]. Q gets 1/sqrt(D) folded in.
// ---------------------------------------------------------------------------
__global__ __launch_bounds__(256) void rope_scatter_bf16()
{
    const int idx = blockIdx.x * blockDim.x + threadIdx.x;
    const int d = idx & (HD - 1);
    const int l = (idx >> 7) & (LL - 1);
    const int h = (idx >> 18) & (NH - 1);
    const int b = idx >> 22;

    const float* row = g_qkv + (size_t)(b * LL + l) * QKVN;
    const float qv = row[h * HD + d];
    const float kv = row[NH * HD + h * HD + d];
    const float vv = row[2 * NH * HD + h * HD + d];

    const int dm = d & 63;
    const float inv = expf(-((float)(2 * dm) / 128.f) * 9.210340371976184f);
    const float ang = (float)l * inv;
    float s, c;
    sincosf(ang, &s, &c);

    const int p = (d < 64) ? d + 64 : d - 64;
    const float sgn = (d < 64) ? -1.f : 1.f;
    const float qp = row[h * HD + p];
    const float kp = row[NH * HD + h * HD + p];

    const float scale = 0.08838834764831845f;  // 1/sqrt(128)
    const float qr = (qv * c + sgn * qp * s) * scale;
    const float kr = kv * c + sgn * kp * s;

    const size_t o = ((size_t)(b * NH + h) * LL + l) * HD + d;
    __nv_bfloat16 qh = __float2bfloat16(qr);
    __nv_bfloat16 kh = __float2bfloat16(kr);
    __nv_bfloat16 vh = __float2bfloat16(vv);
    g_qh_a[o] = qh;
    g_ql_a[o] = __float2bfloat16(qr - __bfloat162float(qh));
    g_kh_a[o] = kh;
    g_kl_a[o] = __float2bfloat16(kr - __bfloat162float(kh));
    g_vh_a[o] = vh;
    g_vl_a[o] = __float2bfloat16(vv - __bfloat162float(vh));
}

// ---------------------------------------------------------------------------
// Flash attention on mma.sync with bf16 hi/lo split.
// BQ=128 (8 warps x m16), BKV=64, D=128, 256 threads.
// K/V cp.async double-buffered. Output written as bf16 hi/lo [b,l,h*D+d].
// ---------------------------------------------------------------------------
#define AT_SP 136                     // padded row stride in halves (272B)
#define QT_BYTES (128 * AT_SP * 2)    // 34816
#define KT_BYTES (64 * AT_SP * 2)     // 17408
#define ATT_SMEM (2 * QT_BYTES + 2 * 4 * KT_BYTES)   // 208896

__global__ __launch_bounds__(256, 1) void flash_mma(
    const __nv_bfloat16* __restrict__ Qh_, const __nv_bfloat16* __restrict__ Ql_,
    const __nv_bfloat16* __restrict__ Kh_, const __nv_bfloat16* __restrict__ Kl_,
    const __nv_bfloat16* __restrict__ Vh_, const __nv_bfloat16* __restrict__ Vl_,
    __nv_bfloat16* __restrict__ Oh_, __nv_bfloat16* __restrict__ Ol_)
{
    extern __shared__ char smem[];
    const uint32_t sb = smem_u32(smem);
    const uint32_t sQh = sb;
    const uint32_t sKV0 = sb + 2 * QT_BYTES;

    const int tid = threadIdx.x, lane = tid & 31, wid = tid >> 5;
    const int qt = blockIdx.x, bh = blockIdx.y;
    const int b = bh >> 4, h = bh & 15;

    const size_t base = (size_t)bh * LL * HD;
    const __nv_bfloat16* qg[2] = {Qh_ + base + (size_t)qt * 128 * HD,
                                  Ql_ + base + (size_t)qt * 128 * HD};
    const __nv_bfloat16* kvg[4] = {Kh_ + base, Kl_ + base, Vh_ + base, Vl_ + base};

    // Q tiles (hi+lo): 4096 x 16B chunks
#pragma unroll
    for (int i = 0; i < 16; i++) {
        const int seg = tid + i * 256;
        const int t = seg >> 11, r = (seg >> 4) & 127, cc = seg & 15;
        CP_ASYNC16(sQh + t * QT_BYTES + r * 272 + cc * 16, qg[t] + (size_t)r * HD + cc * 8);
    }

#define LOAD_KV(kt, s) do { \
    _Pragma("unroll") \
    for (int i_ = 0; i_ < 16; i_++) { \
        const int seg_ = tid + i_ * 256; \
        const int t_ = seg_ >> 10, r_ = (seg_ >> 4) & 63, c_ = seg_ & 15; \
        CP_ASYNC16(sKV0 + (s) * (4 * KT_BYTES) + t_ * KT_BYTES + r_ * 272 + c_ * 16, \
                   kvg[t_] + (size_t)((kt) * 64 + r_) * HD + c_ * 8); \
    } } while (0)

    const int nk = 2 * qt + 2;
    LOAD_KV(0, 0); CP_COMMIT();   // group also contains Q
    LOAD_KV(1, 1); CP_COMMIT();

    uint32_t qfh[8][4], qfl[8][4];
    float O[16][4];
    float mrow0 = NEGBIG, mrow1 = NEGBIG, lrow0 = 0.f, lrow1 = 0.f;
#pragma unroll
    for (int f = 0; f < 16; f++) { O[f][0] = O[f][1] = O[f][2] = O[f][3] = 0.f; }

    const int r0l = wid * 16 + (lane >> 2);
    const int r0g = qt * 128 + r0l;
    const int r1g = r0g + 8;

    const int brow = (lane & 7) + ((lane >> 4) * 8);
    const int bcolb = ((lane >> 3) & 1) * 8;
    const int vrow = lane & 15, vcolb = (lane >> 4) * 8;

    for (int kt = 0; kt < nk; kt++) {
        if (kt == nk - 1) { CP_WAIT0(); } else { CP_WAIT1(); }
        __syncthreads();

        if (kt == 0) {
#pragma unroll
            for (int kb = 0; kb < 8; kb++) {
                const uint32_t ad = sQh +
                    ((wid * 16 + (lane & 15)) * AT_SP + kb * 16 + (lane >> 4) * 8) * 2;
                ldsm4(qfh[kb], ad);
                ldsm4(qfl[kb], ad + QT_BYTES);
            }
        }

        const uint32_t sK = sKV0 + (kt & 1) * (4 * KT_BYTES);
        const uint32_t sV = sK + 2 * KT_BYTES;

        // ---- S = Q K^T (3-pass split) ----
        float S[8][4];
#pragma unroll
        for (int j = 0; j < 8; j++) S[j][0] = S[j][1] = S[j][2] = S[j][3] = 0.f;

#pragma unroll
        for (int jj = 0; jj < 4; jj++) {
#pragma unroll
            for (int kb = 0; kb < 8; kb++) {
                const uint32_t off = ((jj * 16 + brow) * AT_SP + kb * 16 + bcolb) * 2;
                uint32_t kh[4], kl[4];
                ldsm4(kh, sK + off);
                ldsm4(kl, sK + KT_BYTES + off);
                mma_bf16(S[2 * jj],     qfh[kb], kh);
                mma_bf16(S[2 * jj],     qfh[kb], kl);
                mma_bf16(S[2 * jj],     qfl[kb], kh);
                mma_bf16(S[2 * jj + 1], qfh[kb], kh + 2);
                mma_bf16(S[2 * jj + 1], qfh[kb], kl + 2);
                mma_bf16(S[2 * jj + 1], qfl[kb], kh + 2);
            }
        }

        // ---- causal mask (only tiles overlapping the diagonal) ----
        if (kt >= 2 * qt) {
            const int cb = kt * 64 + (lane & 3) * 2;
#pragma unroll
            for (int j = 0; j < 8; j++) {
                const int c0 = cb + j * 8, c1 = c0 + 1;
                if (c0 > r0g) S[j][0] = NEGBIG;
                if (c1 > r0g) S[j][1] = NEGBIG;
                if (c0 > r1g) S[j][2] = NEGBIG;
                if (c1 > r1g) S[j][3] = NEGBIG;
            }
        }

        // ---- online softmax ----
        float mx0 = NEGBIG, mx1 = NEGBIG;
#pragma unroll
        for (int j = 0; j < 8; j++) {
            mx0 = fmaxf(mx0, fmaxf(S[j][0], S[j][1]));
            mx1 = fmaxf(mx1, fmaxf(S[j][2], S[j][3]));
        }
        mx0 = fmaxf(mx0, __shfl_xor_sync(0xFFFFFFFFu, mx0, 1));
        mx0 = fmaxf(mx0, __shfl_xor_sync(0xFFFFFFFFu, mx0, 2));
        mx1 = fmaxf(mx1, __shfl_xor_sync(0xFFFFFFFFu, mx1, 1));
        mx1 = fmaxf(mx1, __shfl_xor_sync(0xFFFFFFFFu, mx1, 2));
        const float mn0 = fmaxf(mrow0, mx0), mn1 = fmaxf(mrow1, mx1);
        const float a0 = __expf(mrow0 - mn0), a1 = __expf(mrow1 - mn1);
        mrow0 = mn0; mrow1 = mn1;
        float s0 = 0.f, s1 = 0.f;
#pragma unroll
        for (int j = 0; j < 8; j++) {
            S[j][0] = __expf(S[j][0] - mn0);
            S[j][1] = __expf(S[j][1] - mn0);
            S[j][2] = __expf(S[j][2] - mn1);
            S[j][3] = __expf(S[j][3] - mn1);
            s0 += S[j][0] + S[j][1];
            s1 += S[j][2] + S[j][3];
        }
        s0 += __shfl_xor_sync(0xFFFFFFFFu, s0, 1);
        s0 += __shfl_xor_sync(0xFFFFFFFFu, s0, 2);
        s1 += __shfl_xor_sync(0xFFFFFFFFu, s1, 1);
        s1 += __shfl_xor_sync(0xFFFFFFFFu, s1, 2);
        lrow0 = lrow0 * a0 + s0;
        lrow1 = lrow1 * a1 + s1;
#pragma unroll
        for (int f = 0; f < 16; f++) {
            O[f][0] *= a0; O[f][1] *= a0; O[f][2] *= a1; O[f][3] *= a1;
        }

        // ---- O += P V (3-pass split; S frags re-packed as A frags) ----
#pragma unroll
        for (int kb2 = 0; kb2 < 4; kb2++) {
            uint32_t ph[4], pl[4];
            ph[0] = pack_bf16(S[2 * kb2][0], S[2 * kb2][1]);
            ph[1] = pack_bf16(S[2 * kb2][2], S[2 * kb2][3]);
            ph[2] = pack_bf16(S[2 * kb2 + 1][0], S[2 * kb2 + 1][1]);
            ph[3] = pack_bf16(S[2 * kb2 + 1][2], S[2 * kb2 + 1][3]);
            pl[0] = pack_bf16(bf16_res(S[2 * kb2][0]), bf16_res(S[2 * kb2][1]));
            pl[1] = pack_bf16(bf16_res(S[2 * kb2][2]), bf16_res(S[2 * kb2][3]));
            pl[2] = pack_bf16(bf16_res(S[2 * kb2 + 1][0]), bf16_res(S[2 * kb2 + 1][1]));
            pl[3] = pack_bf16(bf16_res(S[2 * kb2 + 1][2]), bf16_res(S[2 * kb2 + 1][3]));
#pragma unroll
            for (int dn = 0; dn < 8; dn++) {
                const uint32_t off = ((kb2 * 16 + vrow) * AT_SP + dn * 16 + vcolb) * 2;
                uint32_t vh[4], vl[4];
                ldsm4t(vh, sV + off);
                ldsm4t(vl, sV + KT_BYTES + off);
                mma_bf16(O[2 * dn],     ph, vh);
                mma_bf16(O[2 * dn],     ph, vl);
                mma_bf16(O[2 * dn],     pl, vh);
                mma_bf16(O[2 * dn + 1], ph, vh + 2);
                mma_bf16(O[2 * dn + 1], ph, vl + 2);
                mma_bf16(O[2 * dn + 1], pl, vh + 2);
            }
        }
        __syncthreads();
        if (kt + 2 < nk) { LOAD_KV(kt + 2, kt & 1); CP_COMMIT(); }
    }

    // ---- epilogue: normalize, bf16 hi/lo split, write [b,l,h*D+d] ----
    const float inv0 = 1.f / lrow0, inv1 = 1.f / lrow1;
    const int colb = (lane & 3) * 2;
    const size_t rowbase = ((size_t)(b * LL) + qt * 128 + r0l) * (NH * HD) + h * HD;
#pragma unroll
    for (int f = 0; f < 16; f++) {
        const size_t o0 = rowbase + f * 8 + colb;
        const size_t o1 = o0 + (size_t)8 * (NH * HD);
        const float x0 = O[f][0] * inv0, x1 = O[f][1] * inv0;
        const float x2 = O[f][2] * inv1, x3 = O[f][3] * inv1;
        const __nv_bfloat16 h0 = __float2bfloat16(x0), h1 = __float2bfloat16(x1);
        const __nv_bfloat16 h2v = __float2bfloat16(x2), h3 = __float2bfloat16(x3);
        *(__nv_bfloat162*)(Oh_ + o0) = __nv_bfloat162(h0, h1);
        *(__nv_bfloat162*)(Oh_ + o1) = __nv_bfloat162(h2v, h3);
        *(__nv_bfloat162*)(Ol_ + o0) = __nv_bfloat162(
            __float2bfloat16(x0 - __bfloat162float(h0)),
            __float2bfloat16(x1 - __bfloat162float(h1)));
        *(__nv_bfloat162*)(Ol_ + o1) = __nv_bfloat162(
            __float2bfloat16(x2 - __bfloat162float(h2v)),
            __float2bfloat16(x3 - __bfloat162float(h3)));
    }
}

// ---------------------------------------------------------------------------
extern "C" void kernel_launch(void* const* d_in, const int* in_sizes, int n_in,
                              void* d_out, int out_size)
{
    const float* x    = (const float*)d_in[0];
    const float* Wqkv = (const float*)d_in[1];
    const float* Wo   = (const float*)d_in[2];
    float* out = (float*)d_out;

    float* qkv;
    __nv_bfloat16 *xh, *xl, *wqh, *wql, *woh, *wol, *ah, *al;
    __nv_bfloat16 *qh, *ql, *kh, *kl, *vh, *vl;
    cudaGetSymbolAddress((void**)&qkv, g_qkv);
    cudaGetSymbolAddress((void**)&xh,  g_xh);
    cudaGetSymbolAddress((void**)&xl,  g_xl);
    cudaGetSymbolAddress((void**)&wqh, g_wqh);
    cudaGetSymbolAddress((void**)&wql, g_wql);
    cudaGetSymbolAddress((void**)&woh, g_woh);
    cudaGetSymbolAddress((void**)&wol, g_wol);
    cudaGetSymbolAddress((void**)&ah,  g_ah);
    cudaGetSymbolAddress((void**)&al,  g_al);
    cudaGetSymbolAddress((void**)&qh,  g_qh_a);
    cudaGetSymbolAddress((void**)&ql,  g_ql_a);
    cudaGetSymbolAddress((void**)&kh,  g_kh_a);
    cudaGetSymbolAddress((void**)&kl,  g_kl_a);
    cudaGetSymbolAddress((void**)&vh,  g_vh_a);
    cudaGetSymbolAddress((void**)&vl,  g_vl_a);

    cudaFuncSetAttribute(gemm_mma,
                         cudaFuncAttributeMaxDynamicSharedMemorySize, GEMM_SMEM);
    cudaFuncSetAttribute(flash_mma,
                         cudaFuncAttributeMaxDynamicSharedMemorySize, ATT_SMEM);

    // Prep
    split_bf16<<<(MROWS * HIDDEN) / (256 * 4), 256>>>(x, xh, xl);
    wsplit_T<<<dim3(QKVN / 32, HIDDEN / 32), dim3(32, 8)>>>(Wqkv, wqh, wql, HIDDEN, QKVN);
    wsplit_T<<<dim3(HIDDEN / 32, HIDDEN / 32), dim3(32, 8)>>>(Wo, woh, wol, HIDDEN, HIDDEN);

    // 1) QKV projection
    gemm_mma<<<dim3(MROWS / 128, QKVN / 128), 256, GEMM_SMEM>>>(
        xh, xl, wqh, wql, qkv, HIDDEN, QKVN);

    // 2) RoPE + scatter to bf16 hi/lo
    rope_scatter_bf16<<<(BB * NH * LL * HD) / 256, 256>>>();

    // 3) Causal flash attention on tensor cores
    flash_mma<<<dim3(LL / 128, BB * NH), 256, ATT_SMEM>>>(
        qh, ql, kh, kl, vh, vl, ah, al);

    // 4) Output projection
    gemm_mma<<<dim3(MROWS / 128, HIDDEN / 128), 256, GEMM_SMEM>>>(
        ah, al, woh, wol, out, HIDDEN, HIDDEN);
}

// round 7
// speedup vs baseline: 3.3777x; 1.1727x over previous
#include <cuda_runtime.h>
#include <cuda_bf16.h>
#include <stdint.h>
#include <math.h>

// Problem constants
#define BB 4
#define LL 2048
#define HIDDEN 2048
#define NH 16
#define HD 128
#define MROWS (BB * LL)          // 8192
#define QKVN (3 * NH * HD)       // 6144
#define NEGBIG -1e30f

// Scratch
__device__ float g_qkv[(size_t)MROWS * QKVN];

__device__ __nv_bfloat16 g_xh[(size_t)MROWS * HIDDEN];
__device__ __nv_bfloat16 g_xl[(size_t)MROWS * HIDDEN];
__device__ __nv_bfloat16 g_wqh[(size_t)QKVN * HIDDEN];   // Wqkv^T
__device__ __nv_bfloat16 g_wql[(size_t)QKVN * HIDDEN];
__device__ __nv_bfloat16 g_woh[(size_t)HIDDEN * HIDDEN]; // Wo^T
__device__ __nv_bfloat16 g_wol[(size_t)HIDDEN * HIDDEN];
__device__ __nv_bfloat16 g_ah[(size_t)MROWS * HIDDEN];   // attention out hi/lo
__device__ __nv_bfloat16 g_al[(size_t)MROWS * HIDDEN];

// Q/K/V bf16 hi/lo, layout [b,h,l,d]
#define QKV_ELEMS ((size_t)BB * NH * LL * HD)
__device__ __nv_bfloat16 g_qh_a[QKV_ELEMS];
__device__ __nv_bfloat16 g_ql_a[QKV_ELEMS];
__device__ __nv_bfloat16 g_kh_a[QKV_ELEMS];
__device__ __nv_bfloat16 g_kl_a[QKV_ELEMS];
__device__ __nv_bfloat16 g_vh_a[QKV_ELEMS];
__device__ __nv_bfloat16 g_vl_a[QKV_ELEMS];

// ---------------------------------------------------------------------------
// Helpers (base ISA: cp.async, ldmatrix, mma.sync)
// ---------------------------------------------------------------------------
__device__ __forceinline__ uint32_t smem_u32(const void* p) {
    uint32_t a;
    asm("{ .reg .u64 t; cvta.to.shared.u64 t, %1; cvt.u32.u64 %0, t; }"
        : "=r"(a) : "l"(p));
    return a;
}

#define CP_ASYNC16(dst, src) \
    asm volatile("cp.async.cg.shared.global [%0], [%1], 16;\n" \
                 :: "r"(dst), "l"(src))
#define CP_COMMIT() asm volatile("cp.async.commit_group;\n" ::: "memory")
#define CP_WAIT0()  asm volatile("cp.async.wait_group 0;\n" ::: "memory")
#define CP_WAIT1()  asm volatile("cp.async.wait_group 1;\n" ::: "memory")

__device__ __forceinline__ void ldsm4(uint32_t* r, uint32_t addr) {
    asm volatile("ldmatrix.sync.aligned.m8n8.x4.shared.b16 {%0,%1,%2,%3}, [%4];\n"
                 : "=r"(r[0]), "=r"(r[1]), "=r"(r[2]), "=r"(r[3]) : "r"(addr));
}
__device__ __forceinline__ void ldsm4t(uint32_t* r, uint32_t addr) {
    asm volatile("ldmatrix.sync.aligned.m8n8.x4.trans.shared.b16 {%0,%1,%2,%3}, [%4];\n"
                 : "=r"(r[0]), "=r"(r[1]), "=r"(r[2]), "=r"(r[3]) : "r"(addr));
}

__device__ __forceinline__ void mma_bf16(float* d, const uint32_t* a, const uint32_t* b) {
    asm volatile("mma.sync.aligned.m16n8k16.row.col.f32.bf16.bf16.f32 "
                 "{%0,%1,%2,%3}, {%4,%5,%6,%7}, {%8,%9}, {%0,%1,%2,%3};\n"
                 : "+f"(d[0]), "+f"(d[1]), "+f"(d[2]), "+f"(d[3])
                 : "r"(a[0]), "r"(a[1]), "r"(a[2]), "r"(a[3]),
                   "r"(b[0]), "r"(b[1]));
}

__device__ __forceinline__ uint32_t pack_bf16(float a, float b) {
    __nv_bfloat162 t = __floats2bfloat162_rn(a, b);
    return *(uint32_t*)&t;
}
__device__ __forceinline__ float bf16_res(float a) {
    return a - __bfloat162float(__float2bfloat16(a));
}

// ---------------------------------------------------------------------------
// bf16-split GEMM via mma.sync. 2 CTAs/SM (regs clamped to 128).
// ---------------------------------------------------------------------------
#define SSTR 40
#define TILE_BYTES (128 * SSTR * 2)         // 10240
#define STAGE_BYTES (4 * TILE_BYTES)        // 40960
#define GEMM_SMEM (2 * STAGE_BYTES)         // 81920

__global__ __launch_bounds__(256, 2) void gemm_mma(
    const __nv_bfloat16* __restrict__ Ah, const __nv_bfloat16* __restrict__ Al,
    const __nv_bfloat16* __restrict__ Bh, const __nv_bfloat16* __restrict__ Bl,
    float* __restrict__ C, int Kdim, int Ndim)
{
    extern __shared__ char smem[];
    const uint32_t sbase = smem_u32(smem);
    const int tid = threadIdx.x;
    const int lane = tid & 31;
    const int wid = tid >> 5;
    const int warp_m = (wid >> 1) * 32;
    const int warp_n = (wid & 1) * 64;
    const int mt = blockIdx.x;
    const int nt = blockIdx.y;

    const __nv_bfloat16* gp[4];
    gp[0] = Ah + (size_t)mt * 128 * Kdim;
    gp[1] = Al + (size_t)mt * 128 * Kdim;
    gp[2] = Bh + (size_t)nt * 128 * Kdim;
    gp[3] = Bl + (size_t)nt * 128 * Kdim;

    const int NKC = Kdim >> 5;

#define LOAD_STAGE(c, s) do { \
    const uint32_t sb_ = sbase + (s) * STAGE_BYTES; \
    _Pragma("unroll") \
    for (int t_ = 0; t_ < 4; t_++) { \
        _Pragma("unroll") \
        for (int i_ = 0; i_ < 2; i_++) { \
            const int seg_ = tid + i_ * 256; \
            const int r_ = seg_ >> 2; \
            const int cs_ = (seg_ & 3) * 8; \
            const uint32_t dst_ = sb_ + t_ * TILE_BYTES + (r_ * SSTR + cs_) * 2; \
            const __nv_bfloat16* src_ = gp[t_] + (size_t)r_ * Kdim + (c) * 32 + cs_; \
            CP_ASYNC16(dst_, src_); \
        } \
    } \
} while (0)

    float acc[2][8][4];
#pragma unroll
    for (int mf = 0; mf < 2; mf++)
#pragma unroll
        for (int nf = 0; nf < 8; nf++)
#pragma unroll
            for (int e = 0; e < 4; e++) acc[mf][nf][e] = 0.f;

    LOAD_STAGE(0, 0);
    CP_COMMIT();

    const int arow = lane & 15;
    const int acolb = (lane >> 4) * 8;
    const int brow = (lane & 7) + ((lane >> 4) * 8);
    const int bcolb = ((lane >> 3) & 1) * 8;

    for (int c = 0; c < NKC; c++) {
        CP_WAIT0();
        __syncthreads();
        if (c + 1 < NKC) {
            LOAD_STAGE(c + 1, (c + 1) & 1);
            CP_COMMIT();
        }
        const uint32_t sb = sbase + (c & 1) * STAGE_BYTES;

#pragma unroll
        for (int kk = 0; kk < 2; kk++) {
            uint32_t a_h[2][4], a_l[2][4];
#pragma unroll
            for (int mf = 0; mf < 2; mf++) {
                const uint32_t ad = sb +
                    ((warp_m + mf * 16 + arow) * SSTR + acolb + kk * 16) * 2;
                ldsm4(a_h[mf], ad);
                ldsm4(a_l[mf], ad + TILE_BYTES);
            }
            uint32_t b_h[8][2], b_l[8][2];
#pragma unroll
            for (int np = 0; np < 4; np++) {
                const uint32_t bd = sb + 2 * TILE_BYTES +
                    ((warp_n + np * 16 + brow) * SSTR + bcolb + kk * 16) * 2;
                uint32_t r[4];
                ldsm4(r, bd);
                b_h[np * 2][0] = r[0]; b_h[np * 2][1] = r[1];
                b_h[np * 2 + 1][0] = r[2]; b_h[np * 2 + 1][1] = r[3];
                ldsm4(r, bd + TILE_BYTES);
                b_l[np * 2][0] = r[0]; b_l[np * 2][1] = r[1];
                b_l[np * 2 + 1][0] = r[2]; b_l[np * 2 + 1][1] = r[3];
            }
#pragma unroll
            for (int mf = 0; mf < 2; mf++)
#pragma unroll
                for (int nf = 0; nf < 8; nf++) {
                    mma_bf16(acc[mf][nf], a_h[mf], b_h[nf]);
                    mma_bf16(acc[mf][nf], a_h[mf], b_l[nf]);
                    mma_bf16(acc[mf][nf], a_l[mf], b_h[nf]);
                }
        }
        __syncthreads();
    }

    const int row_base = mt * 128 + warp_m + (lane >> 2);
    const int col_base = nt * 128 + warp_n + (lane & 3) * 2;
#pragma unroll
    for (int mf = 0; mf < 2; mf++)
#pragma unroll
        for (int nf = 0; nf < 8; nf++) {
            const int r0 = row_base + mf * 16;
            const int cc = col_base + nf * 8;
            *(float2*)(C + (size_t)r0 * Ndim + cc) =
                make_float2(acc[mf][nf][0], acc[mf][nf][1]);
            *(float2*)(C + (size_t)(r0 + 8) * Ndim + cc) =
                make_float2(acc[mf][nf][2], acc[mf][nf][3]);
        }
}

// ---------------------------------------------------------------------------
// fp32 -> bf16 hi/lo split (elementwise)
// ---------------------------------------------------------------------------
__global__ __launch_bounds__(256) void split_bf16(
    const float* __restrict__ in, __nv_bfloat16* __restrict__ hi,
    __nv_bfloat16* __restrict__ lo)
{
    const size_t i = (size_t)blockIdx.x * 256 + threadIdx.x;
    float4 v = *(const float4*)(in + i * 4);
    __nv_bfloat16 hx = __float2bfloat16(v.x);
    __nv_bfloat16 hy = __float2bfloat16(v.y);
    __nv_bfloat16 hz = __float2bfloat16(v.z);
    __nv_bfloat16 hw = __float2bfloat16(v.w);
    __nv_bfloat162* h2 = (__nv_bfloat162*)hi;
    __nv_bfloat162* l2 = (__nv_bfloat162*)lo;
    h2[i * 2 + 0] = __nv_bfloat162(hx, hy);
    h2[i * 2 + 1] = __nv_bfloat162(hz, hw);
    l2[i * 2 + 0] = __nv_bfloat162(__float2bfloat16(v.x - __bfloat162float(hx)),
                                   __float2bfloat16(v.y - __bfloat162float(hy)));
    l2[i * 2 + 1] = __nv_bfloat162(__float2bfloat16(v.z - __bfloat162float(hz)),
                                   __float2bfloat16(v.w - __bfloat162float(hw)));
}

// ---------------------------------------------------------------------------
// W[K,N] fp32 -> W^T[N,K] bf16 hi/lo
// ---------------------------------------------------------------------------
__global__ __launch_bounds__(256) void wsplit_T(
    const float* __restrict__ W, __nv_bfloat16* __restrict__ hiT,
    __nv_bfloat16* __restrict__ loT, int Kdim, int Ndim)
{
    __shared__ float sm[32][33];
    const int n0 = blockIdx.x * 32;
    const int k0 = blockIdx.y * 32;
    const int tx = threadIdx.x;
    const int ty = threadIdx.y;
#pragma unroll
    for (int j = 0; j < 4; j++) {
        const int r = ty + j * 8;
        sm[r][tx] = W[(size_t)(k0 + r) * Ndim + n0 + tx];
    }
    __syncthreads();
#pragma unroll
    for (int j = 0; j < 4; j++) {
        const int rt = ty + j * 8;
        const int n = n0 + rt;
        const int k = k0 + tx;
        const float v = sm[tx][rt];
        const __nv_bfloat16 h = __float2bfloat16(v);
        hiT[(size_t)n * Kdim + k] = h;
        loT[(size_t)n * Kdim + k] = __float2bfloat16(v - __bfloat162float(h));
    }
}

// ---------------------------------------------------------------------------
// RoPE + scatter to bf16 hi/lo [b,h,l,d].
// Q gets (1/sqrt(D)) * log2(e) folded in -> softmax uses exp2.
// ---------------------------------------------------------------------------
__global__ __launch_bounds__(256) void rope_scatter_bf16()
{
    const int idx = blockIdx.x * blockDim.x + threadIdx.x;
    const int d = idx & (HD - 1);
    const int l = (idx >> 7) & (LL - 1);
    const int h = (idx >> 18) & (NH - 1);
    const int b = idx >> 22;

    const float* row = g_qkv + (size_t)(b * LL + l) * QKVN;
    const float qv = row[h * HD + d];
    const float kv = row[NH * HD + h * HD + d];
    const float vv = row[2 * NH * HD + h * HD + d];

    const int dm = d & 63;
    const float inv = expf(-((float)(2 * dm) / 128.f) * 9.210340371976184f);
    const float ang = (float)l * inv;
    float s, c;
    sincosf(ang, &s, &c);

    const int p = (d < 64) ? d + 64 : d - 64;
    const float sgn = (d < 64) ? -1.f : 1.f;
    const float qp = row[h * HD + p];
    const float kp = row[NH * HD + h * HD + p];

    // 1/sqrt(128) * log2(e)
    const float scale = 0.08838834764831845f * 1.4426950408889634f;
    const float qr = (qv * c + sgn * qp * s) * scale;
    const float kr = kv * c + sgn * kp * s;

    const size_t o = ((size_t)(b * NH + h) * LL + l) * HD + d;
    __nv_bfloat16 qh = __float2bfloat16(qr);
    __nv_bfloat16 kh = __float2bfloat16(kr);
    __nv_bfloat16 vh = __float2bfloat16(vv);
    g_qh_a[o] = qh;
    g_ql_a[o] = __float2bfloat16(qr - __bfloat162float(qh));
    g_kh_a[o] = kh;
    g_kl_a[o] = __float2bfloat16(kr - __bfloat162float(kh));
    g_vh_a[o] = vh;
    g_vl_a[o] = __float2bfloat16(vv - __bfloat162float(vh));
}

// ---------------------------------------------------------------------------
// Flash attention on mma.sync with bf16 hi/lo split. Base-2 softmax.
// BQ=128 (8 warps x m16), BKV=64, D=128, 256 threads.
// ---------------------------------------------------------------------------
#define AT_SP 136
#define QT_BYTES (128 * AT_SP * 2)    // 34816
#define KT_BYTES (64 * AT_SP * 2)     // 17408
#define ATT_SMEM (2 * QT_BYTES + 2 * 4 * KT_BYTES)   // 208896

__global__ __launch_bounds__(256, 1) void flash_mma(
    const __nv_bfloat16* __restrict__ Qh_, const __nv_bfloat16* __restrict__ Ql_,
    const __nv_bfloat16* __restrict__ Kh_, const __nv_bfloat16* __restrict__ Kl_,
    const __nv_bfloat16* __restrict__ Vh_, const __nv_bfloat16* __restrict__ Vl_,
    __nv_bfloat16* __restrict__ Oh_, __nv_bfloat16* __restrict__ Ol_)
{
    extern __shared__ char smem[];
    const uint32_t sb = smem_u32(smem);
    const uint32_t sQh = sb;
    const uint32_t sKV0 = sb + 2 * QT_BYTES;

    const int tid = threadIdx.x, lane = tid & 31, wid = tid >> 5;
    const int qt = blockIdx.x, bh = blockIdx.y;
    const int b = bh >> 4, h = bh & 15;

    const size_t base = (size_t)bh * LL * HD;
    const __nv_bfloat16* qg[2] = {Qh_ + base + (size_t)qt * 128 * HD,
                                  Ql_ + base + (size_t)qt * 128 * HD};
    const __nv_bfloat16* kvg[4] = {Kh_ + base, Kl_ + base, Vh_ + base, Vl_ + base};

#pragma unroll
    for (int i = 0; i < 16; i++) {
        const int seg = tid + i * 256;
        const int t = seg >> 11, r = (seg >> 4) & 127, cc = seg & 15;
        CP_ASYNC16(sQh + t * QT_BYTES + r * 272 + cc * 16, qg[t] + (size_t)r * HD + cc * 8);
    }

#define LOAD_KV(kt, s) do { \
    _Pragma("unroll") \
    for (int i_ = 0; i_ < 16; i_++) { \
        const int seg_ = tid + i_ * 256; \
        const int t_ = seg_ >> 10, r_ = (seg_ >> 4) & 63, c_ = seg_ & 15; \
        CP_ASYNC16(sKV0 + (s) * (4 * KT_BYTES) + t_ * KT_BYTES + r_ * 272 + c_ * 16, \
                   kvg[t_] + (size_t)((kt) * 64 + r_) * HD + c_ * 8); \
    } } while (0)

    const int nk = 2 * qt + 2;
    LOAD_KV(0, 0); CP_COMMIT();
    LOAD_KV(1, 1); CP_COMMIT();

    uint32_t qfh[8][4], qfl[8][4];
    float O[16][4];
    float mrow0 = NEGBIG, mrow1 = NEGBIG, lrow0 = 0.f, lrow1 = 0.f;
#pragma unroll
    for (int f = 0; f < 16; f++) { O[f][0] = O[f][1] = O[f][2] = O[f][3] = 0.f; }

    const int r0l = wid * 16 + (lane >> 2);
    const int r0g = qt * 128 + r0l;
    const int r1g = r0g + 8;

    const int brow = (lane & 7) + ((lane >> 4) * 8);
    const int bcolb = ((lane >> 3) & 1) * 8;
    const int vrow = lane & 15, vcolb = (lane >> 4) * 8;

    for (int kt = 0; kt < nk; kt++) {
        if (kt == nk - 1) { CP_WAIT0(); } else { CP_WAIT1(); }
        __syncthreads();

        if (kt == 0) {
#pragma unroll
            for (int kb = 0; kb < 8; kb++) {
                const uint32_t ad = sQh +
                    ((wid * 16 + (lane & 15)) * AT_SP + kb * 16 + (lane >> 4) * 8) * 2;
                ldsm4(qfh[kb], ad);
                ldsm4(qfl[kb], ad + QT_BYTES);
            }
        }

        const uint32_t sK = sKV0 + (kt & 1) * (4 * KT_BYTES);
        const uint32_t sV = sK + 2 * KT_BYTES;

        // ---- S = Q K^T (3-pass split; already includes log2e) ----
        float S[8][4];
#pragma unroll
        for (int j = 0; j < 8; j++) S[j][0] = S[j][1] = S[j][2] = S[j][3] = 0.f;

#pragma unroll
        for (int jj = 0; jj < 4; jj++) {
#pragma unroll
            for (int kb = 0; kb < 8; kb++) {
                const uint32_t off = ((jj * 16 + brow) * AT_SP + kb * 16 + bcolb) * 2;
                uint32_t kh[4], kl[4];
                ldsm4(kh, sK + off);
                ldsm4(kl, sK + KT_BYTES + off);
                mma_bf16(S[2 * jj],     qfh[kb], kh);
                mma_bf16(S[2 * jj],     qfh[kb], kl);
                mma_bf16(S[2 * jj],     qfl[kb], kh);
                mma_bf16(S[2 * jj + 1], qfh[kb], kh + 2);
                mma_bf16(S[2 * jj + 1], qfh[kb], kl + 2);
                mma_bf16(S[2 * jj + 1], qfl[kb], kh + 2);
            }
        }

        // ---- causal mask ----
        if (kt >= 2 * qt) {
            const int cb = kt * 64 + (lane & 3) * 2;
#pragma unroll
            for (int j = 0; j < 8; j++) {
                const int c0 = cb + j * 8, c1 = c0 + 1;
                if (c0 > r0g) S[j][0] = NEGBIG;
                if (c1 > r0g) S[j][1] = NEGBIG;
                if (c0 > r1g) S[j][2] = NEGBIG;
                if (c1 > r1g) S[j][3] = NEGBIG;
            }
        }

        // ---- online softmax (base 2) ----
        float mx0 = NEGBIG, mx1 = NEGBIG;
#pragma unroll
        for (int j = 0; j < 8; j++) {
            mx0 = fmaxf(mx0, fmaxf(S[j][0], S[j][1]));
            mx1 = fmaxf(mx1, fmaxf(S[j][2], S[j][3]));
        }
        mx0 = fmaxf(mx0, __shfl_xor_sync(0xFFFFFFFFu, mx0, 1));
        mx0 = fmaxf(mx0, __shfl_xor_sync(0xFFFFFFFFu, mx0, 2));
        mx1 = fmaxf(mx1, __shfl_xor_sync(0xFFFFFFFFu, mx1, 1));
        mx1 = fmaxf(mx1, __shfl_xor_sync(0xFFFFFFFFu, mx1, 2));
        const float mn0 = fmaxf(mrow0, mx0), mn1 = fmaxf(mrow1, mx1);
        const float a0 = exp2f(mrow0 - mn0), a1 = exp2f(mrow1 - mn1);
        mrow0 = mn0; mrow1 = mn1;
        float s0 = 0.f, s1 = 0.f;
#pragma unroll
        for (int j = 0; j < 8; j++) {
            S[j][0] = exp2f(S[j][0] - mn0);
            S[j][1] = exp2f(S[j][1] - mn0);
            S[j][2] = exp2f(S[j][2] - mn1);
            S[j][3] = exp2f(S[j][3] - mn1);
            s0 += S[j][0] + S[j][1];
            s1 += S[j][2] + S[j][3];
        }
        s0 += __shfl_xor_sync(0xFFFFFFFFu, s0, 1);
        s0 += __shfl_xor_sync(0xFFFFFFFFu, s0, 2);
        s1 += __shfl_xor_sync(0xFFFFFFFFu, s1, 1);
        s1 += __shfl_xor_sync(0xFFFFFFFFu, s1, 2);
        lrow0 = lrow0 * a0 + s0;
        lrow1 = lrow1 * a1 + s1;
#pragma unroll
        for (int f = 0; f < 16; f++) {
            O[f][0] *= a0; O[f][1] *= a0; O[f][2] *= a1; O[f][3] *= a1;
        }

        // ---- O += P V (3-pass split) ----
#pragma unroll
        for (int kb2 = 0; kb2 < 4; kb2++) {
            uint32_t ph[4], pl[4];
            ph[0] = pack_bf16(S[2 * kb2][0], S[2 * kb2][1]);
            ph[1] = pack_bf16(S[2 * kb2][2], S[2 * kb2][3]);
            ph[2] = pack_bf16(S[2 * kb2 + 1][0], S[2 * kb2 + 1][1]);
            ph[3] = pack_bf16(S[2 * kb2 + 1][2], S[2 * kb2 + 1][3]);
            pl[0] = pack_bf16(bf16_res(S[2 * kb2][0]), bf16_res(S[2 * kb2][1]));
            pl[1] = pack_bf16(bf16_res(S[2 * kb2][2]), bf16_res(S[2 * kb2][3]));
            pl[2] = pack_bf16(bf16_res(S[2 * kb2 + 1][0]), bf16_res(S[2 * kb2 + 1][1]));
            pl[3] = pack_bf16(bf16_res(S[2 * kb2 + 1][2]), bf16_res(S[2 * kb2 + 1][3]));
#pragma unroll
            for (int dn = 0; dn < 8; dn++) {
                const uint32_t off = ((kb2 * 16 + vrow) * AT_SP + dn * 16 + vcolb) * 2;
                uint32_t vh[4], vl[4];
                ldsm4t(vh, sV + off);
                ldsm4t(vl, sV + KT_BYTES + off);
                mma_bf16(O[2 * dn],     ph, vh);
                mma_bf16(O[2 * dn],     ph, vl);
                mma_bf16(O[2 * dn],     pl, vh);
                mma_bf16(O[2 * dn + 1], ph, vh + 2);
                mma_bf16(O[2 * dn + 1], ph, vl + 2);
                mma_bf16(O[2 * dn + 1], pl, vh + 2);
            }
        }
        __syncthreads();
        if (kt + 2 < nk) { LOAD_KV(kt + 2, kt & 1); CP_COMMIT(); }
    }

    // ---- epilogue ----
    const float inv0 = 1.f / lrow0, inv1 = 1.f / lrow1;
    const int colb = (lane & 3) * 2;
    const size_t rowbase = ((size_t)(b * LL) + qt * 128 + r0l) * (NH * HD) + h * HD;
#pragma unroll
    for (int f = 0; f < 16; f++) {
        const size_t o0 = rowbase + f * 8 + colb;
        const size_t o1 = o0 + (size_t)8 * (NH * HD);
        const float x0 = O[f][0] * inv0, x1 = O[f][1] * inv0;
        const float x2 = O[f][2] * inv1, x3 = O[f][3] * inv1;
        const __nv_bfloat16 h0 = __float2bfloat16(x0), h1 = __float2bfloat16(x1);
        const __nv_bfloat16 h2v = __float2bfloat16(x2), h3 = __float2bfloat16(x3);
        *(__nv_bfloat162*)(Oh_ + o0) = __nv_bfloat162(h0, h1);
        *(__nv_bfloat162*)(Oh_ + o1) = __nv_bfloat162(h2v, h3);
        *(__nv_bfloat162*)(Ol_ + o0) = __nv_bfloat162(
            __float2bfloat16(x0 - __bfloat162float(h0)),
            __float2bfloat16(x1 - __bfloat162float(h1)));
        *(__nv_bfloat162*)(Ol_ + o1) = __nv_bfloat162(
            __float2bfloat16(x2 - __bfloat162float(h2v)),
            __float2bfloat16(x3 - __bfloat162float(h3)));
    }
}

// ---------------------------------------------------------------------------
extern "C" void kernel_launch(void* const* d_in, const int* in_sizes, int n_in,
                              void* d_out, int out_size)
{
    const float* x    = (const float*)d_in[0];
    const float* Wqkv = (const float*)d_in[1];
    const float* Wo   = (const float*)d_in[2];
    float* out = (float*)d_out;

    float* qkv;
    __nv_bfloat16 *xh, *xl, *wqh, *wql, *woh, *wol, *ah, *al;
    __nv_bfloat16 *qh, *ql, *kh, *kl, *vh, *vl;
    cudaGetSymbolAddress((void**)&qkv, g_qkv);
    cudaGetSymbolAddress((void**)&xh,  g_xh);
    cudaGetSymbolAddress((void**)&xl,  g_xl);
    cudaGetSymbolAddress((void**)&wqh, g_wqh);
    cudaGetSymbolAddress((void**)&wql, g_wql);
    cudaGetSymbolAddress((void**)&woh, g_woh);
    cudaGetSymbolAddress((void**)&wol, g_wol);
    cudaGetSymbolAddress((void**)&ah,  g_ah);
    cudaGetSymbolAddress((void**)&al,  g_al);
    cudaGetSymbolAddress((void**)&qh,  g_qh_a);
    cudaGetSymbolAddress((void**)&ql,  g_ql_a);
    cudaGetSymbolAddress((void**)&kh,  g_kh_a);
    cudaGetSymbolAddress((void**)&kl,  g_kl_a);
    cudaGetSymbolAddress((void**)&vh,  g_vh_a);
    cudaGetSymbolAddress((void**)&vl,  g_vl_a);

    cudaFuncSetAttribute(gemm_mma,
                         cudaFuncAttributeMaxDynamicSharedMemorySize, GEMM_SMEM);
    cudaFuncSetAttribute(flash_mma,
                         cudaFuncAttributeMaxDynamicSharedMemorySize, ATT_SMEM);

    // Prep
    split_bf16<<<(MROWS * HIDDEN) / (256 * 4), 256>>>(x, xh, xl);
    wsplit_T<<<dim3(QKVN / 32, HIDDEN / 32), dim3(32, 8)>>>(Wqkv, wqh, wql, HIDDEN, QKVN);
    wsplit_T<<<dim3(HIDDEN / 32, HIDDEN / 32), dim3(32, 8)>>>(Wo, woh, wol, HIDDEN, HIDDEN);

    // 1) QKV projection
    gemm_mma<<<dim3(MROWS / 128, QKVN / 128), 256, GEMM_SMEM>>>(
        xh, xl, wqh, wql, qkv, HIDDEN, QKVN);

    // 2) RoPE + scatter to bf16 hi/lo (log2e folded into Q)
    rope_scatter_bf16<<<(BB * NH * LL * HD) / 256, 256>>>();

    // 3) Causal flash attention on tensor cores
    flash_mma<<<dim3(LL / 128, BB * NH), 256, ATT_SMEM>>>(
        qh, ql, kh, kl, vh, vl, ah, al);

    // 4) Output projection
    gemm_mma<<<dim3(MROWS / 128, HIDDEN / 128), 256, GEMM_SMEM>>>(
        ah, al, woh, wol, out, HIDDEN, HIDDEN);
}

// round 9
// speedup vs baseline: 3.3846x; 1.0020x over previous
#include <cuda_runtime.h>
#include <cuda_bf16.h>
#include <stdint.h>
#include <math.h>

// Problem constants
#define BB 4
#define LL 2048
#define HIDDEN 2048
#define NH 16
#define HD 128
#define MROWS (BB * LL)          // 8192
#define QKVN (3 * NH * HD)       // 6144
#define NEGBIG -1e30f

// Scratch
__device__ float g_qkv[(size_t)MROWS * QKVN];

__device__ __nv_bfloat16 g_xh[(size_t)MROWS * HIDDEN];
__device__ __nv_bfloat16 g_xl[(size_t)MROWS * HIDDEN];
__device__ __nv_bfloat16 g_wqh[(size_t)QKVN * HIDDEN];   // Wqkv^T
__device__ __nv_bfloat16 g_wql[(size_t)QKVN * HIDDEN];
__device__ __nv_bfloat16 g_woh[(size_t)HIDDEN * HIDDEN]; // Wo^T
__device__ __nv_bfloat16 g_wol[(size_t)HIDDEN * HIDDEN];
__device__ __nv_bfloat16 g_ah[(size_t)MROWS * HIDDEN];   // attention out hi/lo
__device__ __nv_bfloat16 g_al[(size_t)MROWS * HIDDEN];

// Q/K/V bf16 hi/lo, layout [b,h,l,d]
#define QKV_ELEMS ((size_t)BB * NH * LL * HD)
__device__ __nv_bfloat16 g_qh_a[QKV_ELEMS];
__device__ __nv_bfloat16 g_ql_a[QKV_ELEMS];
__device__ __nv_bfloat16 g_kh_a[QKV_ELEMS];
__device__ __nv_bfloat16 g_kl_a[QKV_ELEMS];
__device__ __nv_bfloat16 g_vh_a[QKV_ELEMS];
__device__ __nv_bfloat16 g_vl_a[QKV_ELEMS];

// ---------------------------------------------------------------------------
// Helpers (base ISA: cp.async, ldmatrix, mma.sync)
// ---------------------------------------------------------------------------
__device__ __forceinline__ uint32_t smem_u32(const void* p) {
    uint32_t a;
    asm("{ .reg .u64 t; cvta.to.shared.u64 t, %1; cvt.u32.u64 %0, t; }"
        : "=r"(a) : "l"(p));
    return a;
}

#define CP_ASYNC16(dst, src) \
    asm volatile("cp.async.cg.shared.global [%0], [%1], 16;\n" \
                 :: "r"(dst), "l"(src))
#define CP_COMMIT() asm volatile("cp.async.commit_group;\n" ::: "memory")
#define CP_WAIT0()  asm volatile("cp.async.wait_group 0;\n" ::: "memory")
#define CP_WAIT1()  asm volatile("cp.async.wait_group 1;\n" ::: "memory")
#define CP_WAIT2()  asm volatile("cp.async.wait_group 2;\n" ::: "memory")

__device__ __forceinline__ void ldsm4(uint32_t* r, uint32_t addr) {
    asm volatile("ldmatrix.sync.aligned.m8n8.x4.shared.b16 {%0,%1,%2,%3}, [%4];\n"
                 : "=r"(r[0]), "=r"(r[1]), "=r"(r[2]), "=r"(r[3]) : "r"(addr));
}
__device__ __forceinline__ void ldsm4t(uint32_t* r, uint32_t addr) {
    asm volatile("ldmatrix.sync.aligned.m8n8.x4.trans.shared.b16 {%0,%1,%2,%3}, [%4];\n"
                 : "=r"(r[0]), "=r"(r[1]), "=r"(r[2]), "=r"(r[3]) : "r"(addr));
}

__device__ __forceinline__ void mma_bf16(float* d, const uint32_t* a, const uint32_t* b) {
    asm volatile("mma.sync.aligned.m16n8k16.row.col.f32.bf16.bf16.f32 "
                 "{%0,%1,%2,%3}, {%4,%5,%6,%7}, {%8,%9}, {%0,%1,%2,%3};\n"
                 : "+f"(d[0]), "+f"(d[1]), "+f"(d[2]), "+f"(d[3])
                 : "r"(a[0]), "r"(a[1]), "r"(a[2]), "r"(a[3]),
                   "r"(b[0]), "r"(b[1]));
}

__device__ __forceinline__ uint32_t pack_bf16(float a, float b) {
    __nv_bfloat162 t = __floats2bfloat162_rn(a, b);
    return *(uint32_t*)&t;
}
__device__ __forceinline__ float bf16_res(float a) {
    return a - __bfloat162float(__float2bfloat16(a));
}

// ---------------------------------------------------------------------------
// bf16-split GEMM via mma.sync. 2 CTAs/SM (regs clamped to 128). (R7-verified)
// ---------------------------------------------------------------------------
#define SSTR 40
#define TILE_BYTES (128 * SSTR * 2)         // 10240
#define STAGE_BYTES (4 * TILE_BYTES)        // 40960
#define GEMM_SMEM (2 * STAGE_BYTES)         // 81920

__global__ __launch_bounds__(256, 2) void gemm_mma(
    const __nv_bfloat16* __restrict__ Ah, const __nv_bfloat16* __restrict__ Al,
    const __nv_bfloat16* __restrict__ Bh, const __nv_bfloat16* __restrict__ Bl,
    float* __restrict__ C, int Kdim, int Ndim)
{
    extern __shared__ char smem[];
    const uint32_t sbase = smem_u32(smem);
    const int tid = threadIdx.x;
    const int lane = tid & 31;
    const int wid = tid >> 5;
    const int warp_m = (wid >> 1) * 32;
    const int warp_n = (wid & 1) * 64;
    const int mt = blockIdx.x;
    const int nt = blockIdx.y;

    const __nv_bfloat16* gp[4];
    gp[0] = Ah + (size_t)mt * 128 * Kdim;
    gp[1] = Al + (size_t)mt * 128 * Kdim;
    gp[2] = Bh + (size_t)nt * 128 * Kdim;
    gp[3] = Bl + (size_t)nt * 128 * Kdim;

    const int NKC = Kdim >> 5;

#define LOAD_STAGE(c, s) do { \
    const uint32_t sb_ = sbase + (s) * STAGE_BYTES; \
    _Pragma("unroll") \
    for (int t_ = 0; t_ < 4; t_++) { \
        _Pragma("unroll") \
        for (int i_ = 0; i_ < 2; i_++) { \
            const int seg_ = tid + i_ * 256; \
            const int r_ = seg_ >> 2; \
            const int cs_ = (seg_ & 3) * 8; \
            const uint32_t dst_ = sb_ + t_ * TILE_BYTES + (r_ * SSTR + cs_) * 2; \
            const __nv_bfloat16* src_ = gp[t_] + (size_t)r_ * Kdim + (c) * 32 + cs_; \
            CP_ASYNC16(dst_, src_); \
        } \
    } \
} while (0)

    float acc[2][8][4];
#pragma unroll
    for (int mf = 0; mf < 2; mf++)
#pragma unroll
        for (int nf = 0; nf < 8; nf++)
#pragma unroll
            for (int e = 0; e < 4; e++) acc[mf][nf][e] = 0.f;

    LOAD_STAGE(0, 0);
    CP_COMMIT();

    const int arow = lane & 15;
    const int acolb = (lane >> 4) * 8;
    const int brow = (lane & 7) + ((lane >> 4) * 8);
    const int bcolb = ((lane >> 3) & 1) * 8;

    for (int c = 0; c < NKC; c++) {
        CP_WAIT0();
        __syncthreads();
        if (c + 1 < NKC) {
            LOAD_STAGE(c + 1, (c + 1) & 1);
            CP_COMMIT();
        }
        const uint32_t sb = sbase + (c & 1) * STAGE_BYTES;

#pragma unroll
        for (int kk = 0; kk < 2; kk++) {
            uint32_t a_h[2][4], a_l[2][4];
#pragma unroll
            for (int mf = 0; mf < 2; mf++) {
                const uint32_t ad = sb +
                    ((warp_m + mf * 16 + arow) * SSTR + acolb + kk * 16) * 2;
                ldsm4(a_h[mf], ad);
                ldsm4(a_l[mf], ad + TILE_BYTES);
            }
            uint32_t b_h[8][2], b_l[8][2];
#pragma unroll
            for (int np = 0; np < 4; np++) {
                const uint32_t bd = sb + 2 * TILE_BYTES +
                    ((warp_n + np * 16 + brow) * SSTR + bcolb + kk * 16) * 2;
                uint32_t r[4];
                ldsm4(r, bd);
                b_h[np * 2][0] = r[0]; b_h[np * 2][1] = r[1];
                b_h[np * 2 + 1][0] = r[2]; b_h[np * 2 + 1][1] = r[3];
                ldsm4(r, bd + TILE_BYTES);
                b_l[np * 2][0] = r[0]; b_l[np * 2][1] = r[1];
                b_l[np * 2 + 1][0] = r[2]; b_l[np * 2 + 1][1] = r[3];
            }
#pragma unroll
            for (int mf = 0; mf < 2; mf++)
#pragma unroll
                for (int nf = 0; nf < 8; nf++) {
                    mma_bf16(acc[mf][nf], a_h[mf], b_h[nf]);
                    mma_bf16(acc[mf][nf], a_h[mf], b_l[nf]);
                    mma_bf16(acc[mf][nf], a_l[mf], b_h[nf]);
                }
        }
        __syncthreads();
    }

    const int row_base = mt * 128 + warp_m + (lane >> 2);
    const int col_base = nt * 128 + warp_n + (lane & 3) * 2;
#pragma unroll
    for (int mf = 0; mf < 2; mf++)
#pragma unroll
        for (int nf = 0; nf < 8; nf++) {
            const int r0 = row_base + mf * 16;
            const int cc = col_base + nf * 8;
            *(float2*)(C + (size_t)r0 * Ndim + cc) =
                make_float2(acc[mf][nf][0], acc[mf][nf][1]);
            *(float2*)(C + (size_t)(r0 + 8) * Ndim + cc) =
                make_float2(acc[mf][nf][2], acc[mf][nf][3]);
        }
}

// ---------------------------------------------------------------------------
// fp32 -> bf16 hi/lo split (elementwise)
// ---------------------------------------------------------------------------
__global__ __launch_bounds__(256) void split_bf16(
    const float* __restrict__ in, __nv_bfloat16* __restrict__ hi,
    __nv_bfloat16* __restrict__ lo)
{
    const size_t i = (size_t)blockIdx.x * 256 + threadIdx.x;
    float4 v = *(const float4*)(in + i * 4);
    __nv_bfloat16 hx = __float2bfloat16(v.x);
    __nv_bfloat16 hy = __float2bfloat16(v.y);
    __nv_bfloat16 hz = __float2bfloat16(v.z);
    __nv_bfloat16 hw = __float2bfloat16(v.w);
    __nv_bfloat162* h2 = (__nv_bfloat162*)hi;
    __nv_bfloat162* l2 = (__nv_bfloat162*)lo;
    h2[i * 2 + 0] = __nv_bfloat162(hx, hy);
    h2[i * 2 + 1] = __nv_bfloat162(hz, hw);
    l2[i * 2 + 0] = __nv_bfloat162(__float2bfloat16(v.x - __bfloat162float(hx)),
                                   __float2bfloat16(v.y - __bfloat162float(hy)));
    l2[i * 2 + 1] = __nv_bfloat162(__float2bfloat16(v.z - __bfloat162float(hz)),
                                   __float2bfloat16(v.w - __bfloat162float(hw)));
}

// ---------------------------------------------------------------------------
// W[K,N] fp32 -> W^T[N,K] bf16 hi/lo
// ---------------------------------------------------------------------------
__global__ __launch_bounds__(256) void wsplit_T(
    const float* __restrict__ W, __nv_bfloat16* __restrict__ hiT,
    __nv_bfloat16* __restrict__ loT, int Kdim, int Ndim)
{
    __shared__ float sm[32][33];
    const int n0 = blockIdx.x * 32;
    const int k0 = blockIdx.y * 32;
    const int tx = threadIdx.x;
    const int ty = threadIdx.y;
#pragma unroll
    for (int j = 0; j < 4; j++) {
        const int r = ty + j * 8;
        sm[r][tx] = W[(size_t)(k0 + r) * Ndim + n0 + tx];
    }
    __syncthreads();
#pragma unroll
    for (int j = 0; j < 4; j++) {
        const int rt = ty + j * 8;
        const int n = n0 + rt;
        const int k = k0 + tx;
        const float v = sm[tx][rt];
        const __nv_bfloat16 h = __float2bfloat16(v);
        hiT[(size_t)n * Kdim + k] = h;
        loT[(size_t)n * Kdim + k] = __float2bfloat16(v - __bfloat162float(h));
    }
}

// ---------------------------------------------------------------------------
// RoPE + scatter to bf16 hi/lo [b,h,l,d].
// Q gets (1/sqrt(D)) * log2(e) folded in -> softmax uses exp2.
// ---------------------------------------------------------------------------
__global__ __launch_bounds__(256) void rope_scatter_bf16()
{
    const int idx = blockIdx.x * blockDim.x + threadIdx.x;
    const int d = idx & (HD - 1);
    const int l = (idx >> 7) & (LL - 1);
    const int h = (idx >> 18) & (NH - 1);
    const int b = idx >> 22;

    const float* row = g_qkv + (size_t)(b * LL + l) * QKVN;
    const float qv = row[h * HD + d];
    const float kv = row[NH * HD + h * HD + d];
    const float vv = row[2 * NH * HD + h * HD + d];

    const int dm = d & 63;
    const float inv = expf(-((float)(2 * dm) / 128.f) * 9.210340371976184f);
    const float ang = (float)l * inv;
    float s, c;
    sincosf(ang, &s, &c);

    const int p = (d < 64) ? d + 64 : d - 64;
    const float sgn = (d < 64) ? -1.f : 1.f;
    const float qp = row[h * HD + p];
    const float kp = row[NH * HD + h * HD + p];

    // 1/sqrt(128) * log2(e)
    const float scale = 0.08838834764831845f * 1.4426950408889634f;
    const float qr = (qv * c + sgn * qp * s) * scale;
    const float kr = kv * c + sgn * kp * s;

    const size_t o = ((size_t)(b * NH + h) * LL + l) * HD + d;
    __nv_bfloat16 qh = __float2bfloat16(qr);
    __nv_bfloat16 kh = __float2bfloat16(kr);
    __nv_bfloat16 vh = __float2bfloat16(vv);
    g_qh_a[o] = qh;
    g_ql_a[o] = __float2bfloat16(qr - __bfloat162float(qh));
    g_kh_a[o] = kh;
    g_kl_a[o] = __float2bfloat16(kr - __bfloat162float(kh));
    g_vh_a[o] = vh;
    g_vl_a[o] = __float2bfloat16(vv - __bfloat162float(vh));
}

// ---------------------------------------------------------------------------
// Flash attention on mma.sync, bf16 hi/lo split, base-2 softmax.
// BQ=128 (8 warps x m16), BKV=64, D=128, 256 threads.
// 3-stage KV pipeline; Q staged through stage 2; one sync per KV tile.
// S: 3-pass split. PV: 3-pass split (Ph*Vh + Ph*Vl + Pl*Vh) — required for 1e-3.
// ---------------------------------------------------------------------------
#define AT_SP 136
#define QT_BYTES (128 * AT_SP * 2)        // 34816 (one tile of Q, hi or lo)
#define KT_BYTES (64 * AT_SP * 2)         // 17408
#define ATT_STAGE (4 * KT_BYTES)          // 69632
#define ATT_SMEM (3 * ATT_STAGE)          // 208896

__global__ __launch_bounds__(256, 1) void flash_mma(
    const __nv_bfloat16* __restrict__ Qh_, const __nv_bfloat16* __restrict__ Ql_,
    const __nv_bfloat16* __restrict__ Kh_, const __nv_bfloat16* __restrict__ Kl_,
    const __nv_bfloat16* __restrict__ Vh_, const __nv_bfloat16* __restrict__ Vl_,
    __nv_bfloat16* __restrict__ Oh_, __nv_bfloat16* __restrict__ Ol_)
{
    extern __shared__ char smem[];
    const uint32_t sKV0 = smem_u32(smem);
    const uint32_t sQ = sKV0 + 2 * ATT_STAGE;   // Q staged in stage 2

    const int tid = threadIdx.x, lane = tid & 31, wid = tid >> 5;
    const int qt = (int)gridDim.x - 1 - (int)blockIdx.x;   // heavy tiles first
    const int bh = blockIdx.y;
    const int b = bh >> 4, h = bh & 15;

    const size_t base = (size_t)bh * LL * HD;
    const __nv_bfloat16* qg[2] = {Qh_ + base + (size_t)qt * 128 * HD,
                                  Ql_ + base + (size_t)qt * 128 * HD};
    const __nv_bfloat16* kvg[4] = {Kh_ + base, Kl_ + base, Vh_ + base, Vl_ + base};

    // Q hi+lo into stage 2 (own commit group)
#pragma unroll
    for (int i = 0; i < 16; i++) {
        const int seg = tid + i * 256;
        const int t = seg >> 11, r = (seg >> 4) & 127, cc = seg & 15;
        CP_ASYNC16(sQ + t * QT_BYTES + r * 272 + cc * 16, qg[t] + (size_t)r * HD + cc * 8);
    }
    CP_COMMIT();

#define LOAD_KV(kt, s) do { \
    _Pragma("unroll") \
    for (int i_ = 0; i_ < 16; i_++) { \
        const int seg_ = tid + i_ * 256; \
        const int t_ = seg_ >> 10, r_ = (seg_ >> 4) & 63, c_ = seg_ & 15; \
        CP_ASYNC16(sKV0 + (s) * ATT_STAGE + t_ * KT_BYTES + r_ * 272 + c_ * 16, \
                   kvg[t_] + (size_t)((kt) * 64 + r_) * HD + c_ * 8); \
    } } while (0)

    const int nk = 2 * qt + 2;
    LOAD_KV(0, 0); CP_COMMIT();
    LOAD_KV(1, 1); CP_COMMIT();

    // Extract Q fragments (retire only the Q group)
    CP_WAIT2();
    __syncthreads();
    uint32_t qfh[8][4], qfl[8][4];
#pragma unroll
    for (int kb = 0; kb < 8; kb++) {
        const uint32_t ad = sQ +
            ((wid * 16 + (lane & 15)) * AT_SP + kb * 16 + (lane >> 4) * 8) * 2;
        ldsm4(qfh[kb], ad);
        ldsm4(qfl[kb], ad + QT_BYTES);
    }

    float O[16][4];
    float mrow0 = NEGBIG, mrow1 = NEGBIG, lrow0 = 0.f, lrow1 = 0.f;
#pragma unroll
    for (int f = 0; f < 16; f++) { O[f][0] = O[f][1] = O[f][2] = O[f][3] = 0.f; }

    const int r0l = wid * 16 + (lane >> 2);
    const int r0g = qt * 128 + r0l;
    const int r1g = r0g + 8;

    const int brow = (lane & 7) + ((lane >> 4) * 8);
    const int bcolb = ((lane >> 3) & 1) * 8;
    const int vrow = lane & 15, vcolb = (lane >> 4) * 8;

    for (int kt = 0; kt < nk; kt++) {
        if (kt + 1 < nk) { CP_WAIT1(); } else { CP_WAIT0(); }
        __syncthreads();
        // Refill the stage last used by KV(kt-1) with KV(kt+2)
        if (kt + 2 < nk) { LOAD_KV(kt + 2, (kt + 2) % 3); CP_COMMIT(); }

        const uint32_t sK = sKV0 + (kt % 3) * ATT_STAGE;
        const uint32_t sV = sK + 2 * KT_BYTES;

        // ---- S = Q K^T (3-pass split; includes log2e) ----
        float S[8][4];
#pragma unroll
        for (int j = 0; j < 8; j++) S[j][0] = S[j][1] = S[j][2] = S[j][3] = 0.f;

#pragma unroll
        for (int jj = 0; jj < 4; jj++) {
#pragma unroll
            for (int kb = 0; kb < 8; kb++) {
                const uint32_t off = ((jj * 16 + brow) * AT_SP + kb * 16 + bcolb) * 2;
                uint32_t kh[4], kl[4];
                ldsm4(kh, sK + off);
                ldsm4(kl, sK + KT_BYTES + off);
                mma_bf16(S[2 * jj],     qfh[kb], kh);
                mma_bf16(S[2 * jj],     qfh[kb], kl);
                mma_bf16(S[2 * jj],     qfl[kb], kh);
                mma_bf16(S[2 * jj + 1], qfh[kb], kh + 2);
                mma_bf16(S[2 * jj + 1], qfh[kb], kl + 2);
                mma_bf16(S[2 * jj + 1], qfl[kb], kh + 2);
            }
        }

        // ---- causal mask ----
        if (kt >= 2 * qt) {
            const int cb = kt * 64 + (lane & 3) * 2;
#pragma unroll
            for (int j = 0; j < 8; j++) {
                const int c0 = cb + j * 8, c1 = c0 + 1;
                if (c0 > r0g) S[j][0] = NEGBIG;
                if (c1 > r0g) S[j][1] = NEGBIG;
                if (c0 > r1g) S[j][2] = NEGBIG;
                if (c1 > r1g) S[j][3] = NEGBIG;
            }
        }

        // ---- online softmax (base 2) ----
        float mx0 = NEGBIG, mx1 = NEGBIG;
#pragma unroll
        for (int j = 0; j < 8; j++) {
            mx0 = fmaxf(mx0, fmaxf(S[j][0], S[j][1]));
            mx1 = fmaxf(mx1, fmaxf(S[j][2], S[j][3]));
        }
        mx0 = fmaxf(mx0, __shfl_xor_sync(0xFFFFFFFFu, mx0, 1));
        mx0 = fmaxf(mx0, __shfl_xor_sync(0xFFFFFFFFu, mx0, 2));
        mx1 = fmaxf(mx1, __shfl_xor_sync(0xFFFFFFFFu, mx1, 1));
        mx1 = fmaxf(mx1, __shfl_xor_sync(0xFFFFFFFFu, mx1, 2));
        const float mn0 = fmaxf(mrow0, mx0), mn1 = fmaxf(mrow1, mx1);
        const float a0 = exp2f(mrow0 - mn0), a1 = exp2f(mrow1 - mn1);
        mrow0 = mn0; mrow1 = mn1;
        float s0 = 0.f, s1 = 0.f;
#pragma unroll
        for (int j = 0; j < 8; j++) {
            S[j][0] = exp2f(S[j][0] - mn0);
            S[j][1] = exp2f(S[j][1] - mn0);
            S[j][2] = exp2f(S[j][2] - mn1);
            S[j][3] = exp2f(S[j][3] - mn1);
            s0 += S[j][0] + S[j][1];
            s1 += S[j][2] + S[j][3];
        }
        s0 += __shfl_xor_sync(0xFFFFFFFFu, s0, 1);
        s0 += __shfl_xor_sync(0xFFFFFFFFu, s0, 2);
        s1 += __shfl_xor_sync(0xFFFFFFFFu, s1, 1);
        s1 += __shfl_xor_sync(0xFFFFFFFFu, s1, 2);
        lrow0 = lrow0 * a0 + s0;
        lrow1 = lrow1 * a1 + s1;
#pragma unroll
        for (int f = 0; f < 16; f++) {
            O[f][0] *= a0; O[f][1] *= a0; O[f][2] *= a1; O[f][3] *= a1;
        }

        // ---- O += P V (3-pass split) ----
#pragma unroll
        for (int kb2 = 0; kb2 < 4; kb2++) {
            uint32_t ph[4], pl[4];
            ph[0] = pack_bf16(S[2 * kb2][0], S[2 * kb2][1]);
            ph[1] = pack_bf16(S[2 * kb2][2], S[2 * kb2][3]);
            ph[2] = pack_bf16(S[2 * kb2 + 1][0], S[2 * kb2 + 1][1]);
            ph[3] = pack_bf16(S[2 * kb2 + 1][2], S[2 * kb2 + 1][3]);
            pl[0] = pack_bf16(bf16_res(S[2 * kb2][0]), bf16_res(S[2 * kb2][1]));
            pl[1] = pack_bf16(bf16_res(S[2 * kb2][2]), bf16_res(S[2 * kb2][3]));
            pl[2] = pack_bf16(bf16_res(S[2 * kb2 + 1][0]), bf16_res(S[2 * kb2 + 1][1]));
            pl[3] = pack_bf16(bf16_res(S[2 * kb2 + 1][2]), bf16_res(S[2 * kb2 + 1][3]));
#pragma unroll
            for (int dn = 0; dn < 8; dn++) {
                const uint32_t off = ((kb2 * 16 + vrow) * AT_SP + dn * 16 + vcolb) * 2;
                uint32_t vh[4], vl[4];
                ldsm4t(vh, sV + off);
                ldsm4t(vl, sV + KT_BYTES + off);
                mma_bf16(O[2 * dn],     ph, vh);
                mma_bf16(O[2 * dn],     ph, vl);
                mma_bf16(O[2 * dn],     pl, vh);
                mma_bf16(O[2 * dn + 1], ph, vh + 2);
                mma_bf16(O[2 * dn + 1], ph, vl + 2);
                mma_bf16(O[2 * dn + 1], pl, vh + 2);
            }
        }
    }

    // ---- epilogue: normalize, bf16 hi/lo split, write [b,l,h*D+d] ----
    const float inv0 = 1.f / lrow0, inv1 = 1.f / lrow1;
    const int colb = (lane & 3) * 2;
    const size_t rowbase = ((size_t)(b * LL) + qt * 128 + r0l) * (NH * HD) + h * HD;
#pragma unroll
    for (int f = 0; f < 16; f++) {
        const size_t o0 = rowbase + f * 8 + colb;
        const size_t o1 = o0 + (size_t)8 * (NH * HD);
        const float x0 = O[f][0] * inv0, x1 = O[f][1] * inv0;
        const float x2 = O[f][2] * inv1, x3 = O[f][3] * inv1;
        const __nv_bfloat16 h0 = __float2bfloat16(x0), h1 = __float2bfloat16(x1);
        const __nv_bfloat16 h2v = __float2bfloat16(x2), h3 = __float2bfloat16(x3);
        *(__nv_bfloat162*)(Oh_ + o0) = __nv_bfloat162(h0, h1);
        *(__nv_bfloat162*)(Oh_ + o1) = __nv_bfloat162(h2v, h3);
        *(__nv_bfloat162*)(Ol_ + o0) = __nv_bfloat162(
            __float2bfloat16(x0 - __bfloat162float(h0)),
            __float2bfloat16(x1 - __bfloat162float(h1)));
        *(__nv_bfloat162*)(Ol_ + o1) = __nv_bfloat162(
            __float2bfloat16(x2 - __bfloat162float(h2v)),
            __float2bfloat16(x3 - __bfloat162float(h3)));
    }
}

// ---------------------------------------------------------------------------
extern "C" void kernel_launch(void* const* d_in, const int* in_sizes, int n_in,
                              void* d_out, int out_size)
{
    const float* x    = (const float*)d_in[0];
    const float* Wqkv = (const float*)d_in[1];
    const float* Wo   = (const float*)d_in[2];
    float* out = (float*)d_out;

    float* qkv;
    __nv_bfloat16 *xh, *xl, *wqh, *wql, *woh, *wol, *ah, *al;
    __nv_bfloat16 *qh, *ql, *kh, *kl, *vh, *vl;
    cudaGetSymbolAddress((void**)&qkv, g_qkv);
    cudaGetSymbolAddress((void**)&xh,  g_xh);
    cudaGetSymbolAddress((void**)&xl,  g_xl);
    cudaGetSymbolAddress((void**)&wqh, g_wqh);
    cudaGetSymbolAddress((void**)&wql, g_wql);
    cudaGetSymbolAddress((void**)&woh, g_woh);
    cudaGetSymbolAddress((void**)&wol, g_wol);
    cudaGetSymbolAddress((void**)&ah,  g_ah);
    cudaGetSymbolAddress((void**)&al,  g_al);
    cudaGetSymbolAddress((void**)&qh,  g_qh_a);
    cudaGetSymbolAddress((void**)&ql,  g_ql_a);
    cudaGetSymbolAddress((void**)&kh,  g_kh_a);
    cudaGetSymbolAddress((void**)&kl,  g_kl_a);
    cudaGetSymbolAddress((void**)&vh,  g_vh_a);
    cudaGetSymbolAddress((void**)&vl,  g_vl_a);

    cudaFuncSetAttribute(gemm_mma,
                         cudaFuncAttributeMaxDynamicSharedMemorySize, GEMM_SMEM);
    cudaFuncSetAttribute(flash_mma,
                         cudaFuncAttributeMaxDynamicSharedMemorySize, ATT_SMEM);

    // Prep
    split_bf16<<<(MROWS * HIDDEN) / (256 * 4), 256>>>(x, xh, xl);
    wsplit_T<<<dim3(QKVN / 32, HIDDEN / 32), dim3(32, 8)>>>(Wqkv, wqh, wql, HIDDEN, QKVN);
    wsplit_T<<<dim3(HIDDEN / 32, HIDDEN / 32), dim3(32, 8)>>>(Wo, woh, wol, HIDDEN, HIDDEN);

    // 1) QKV projection
    gemm_mma<<<dim3(MROWS / 128, QKVN / 128), 256, GEMM_SMEM>>>(
        xh, xl, wqh, wql, qkv, HIDDEN, QKVN);

    // 2) RoPE + scatter to bf16 hi/lo (log2e folded into Q)
    rope_scatter_bf16<<<(BB * NH * LL * HD) / 256, 256>>>();

    // 3) Causal flash attention on tensor cores
    flash_mma<<<dim3(LL / 128, BB * NH), 256, ATT_SMEM>>>(
        qh, ql, kh, kl, vh, vl, ah, al);

    // 4) Output projection
    gemm_mma<<<dim3(MROWS / 128, HIDDEN / 128), 256, GEMM_SMEM>>>(
        ah, al, woh, wol, out, HIDDEN, HIDDEN);
}